// round 13
// baseline (speedup 1.0000x reference)
#include <cuda_runtime.h>
#include <cuda_fp16.h>
#include <math.h>
#include <stdint.h>

#define N_PIX 4096
#define CDIM  256
#define HID   128
#define NH    4
#define DH    32
#define BATCH 2
#define ATT_SCALE 0.17677669529663687f   // 32^-0.5
#define LOG2E     1.4426950408889634f

// ---------------- scratch (static device globals; no allocs) ----------------
__device__ __half g_qh [BATCH * NH * N_PIX * DH];   // [bh][n][f], pre-scaled by ATT_SCALE*LOG2E
__device__ __half g_kh [BATCH * NH * N_PIX * DH];   // [bh][n][f]
__device__ __half g_vh [BATCH * NH * DH * N_PIX];   // [bh][f][n]  (transposed)
__device__ __half g_aoh[BATCH * N_PIX * HID];       // [b][n][h*32+f]  (n-major)
__device__ __half g_wqh[3 * HID * CDIM];            // f16(w_qkv * g)  [o][c]
__device__ __half g_woh[CDIM * HID];                // f16(w_out)      [o][k]

__device__ __forceinline__ uint32_t smem_u32(const void* p) {
    uint32_t a;
    asm("{ .reg .u64 t; cvta.to.shared.u64 t, %1; cvt.u32.u64 %0, t; }" : "=r"(a) : "l"(p));
    return a;
}
__device__ __forceinline__ uint32_t h2u(__half2 h) { return *(uint32_t*)&h; }
__device__ __forceinline__ uint32_t ex2_h2(uint32_t x) {
    uint32_t r;
    asm("ex2.approx.f16x2 %0, %1;" : "=r"(r) : "r"(x));
    return r;
}
__device__ __forceinline__ uint32_t hadd2u(uint32_t a, uint32_t b) {
    uint32_t r;
    asm("add.f16x2 %0, %1, %2;" : "=r"(r) : "r"(a), "r"(b));
    return r;
}

#define MMA_F16(c, a, b0_, b1_) \
    asm volatile("mma.sync.aligned.m16n8k16.row.col.f32.f16.f16.f32 " \
        "{%0,%1,%2,%3},{%4,%5,%6,%7},{%8,%9},{%0,%1,%2,%3};" \
        : "+f"((c)[0]), "+f"((c)[1]), "+f"((c)[2]), "+f"((c)[3]) \
        : "r"((a)[0]), "r"((a)[1]), "r"((a)[2]), "r"((a)[3]), "r"(b0_), "r"(b1_))
#define CP_ASYNC16(dst, src) \
    asm volatile("cp.async.ca.shared.global [%0], [%1], 16;" :: "r"(dst), "l"(src))
#define CP_COMMIT() asm volatile("cp.async.commit_group;" ::: "memory")
#define CP_WAIT0()  asm volatile("cp.async.wait_group 0;"  ::: "memory")

// ---------------- kernel 0: weight pre-conversion ----------------
__global__ void prep_w(const float* __restrict__ wqkv,
                       const float* __restrict__ gvec,
                       const float* __restrict__ wout) {
    int i = blockIdx.x * 256 + threadIdx.x;          // float4 index
    if (i < 24576) {                                 // w_qkv: 384*256/4
        float4 wv = ((const float4*)wqkv)[i];
        int c4 = (i & 63) << 2;
        float4 gv = *(const float4*)&gvec[c4];
        uint2 o;
        o.x = h2u(__floats2half2_rn(wv.x * gv.x, wv.y * gv.y));
        o.y = h2u(__floats2half2_rn(wv.z * gv.z, wv.w * gv.w));
        ((uint2*)g_wqh)[i] = o;
    } else {                                         // w_out: 256*128/4
        int j = i - 24576;
        float4 wv = ((const float4*)wout)[j];
        uint2 o;
        o.x = h2u(__floats2half2_rn(wv.x, wv.y));
        o.y = h2u(__floats2half2_rn(wv.z, wv.w));
        ((uint2*)g_woh)[j] = o;
    }
}

// ---------------- kernel 1: QKV GEMM, 128x64 tiles, cp.async, norm fused ----------------
#define GP 12            // f16 smem pitch in uint32 (8 data + 4 pad)
#define XP 68            // f32 x-staging pitch in floats (64 + 4 pad)
__global__ void __launch_bounds__(256) qkv_mma(const float* __restrict__ x) {
    __shared__ float    Xf[2][16 * XP];
    __shared__ uint32_t As[2][128 * GP];
    __shared__ uint32_t Bs[2][64 * GP];
    __shared__ float ssb[256];
    int b = blockIdx.z, row0 = blockIdx.y * 128, col0 = blockIdx.x * 64;
    int tid = threadIdx.x, wid = tid >> 5, lane = tid & 31;
    int wm = wid >> 2, wn = wid & 3;                 // warp = 64m x 16n
    int g = lane >> 2, tig = lane & 3;
    const float* Bbase = x + (size_t)b * CDIM * N_PIX;

    uint32_t sbX = smem_u32(&Xf[0][0]);
    uint32_t sbA = smem_u32(&As[0][0]);
    int am = tid >> 1, ach = tid & 1;                // A cp: row am, 16B chunk ach
    int xc = tid >> 4, xh = (tid & 15) * 4;          // X cp: c-row xc, floats xh..xh+3
    int bp = tid & 63, bc = tid >> 6;                // stage: pixel bp, c-quad bc (0..3)

#define QKV_CP(it, s) do { \
        int k0q = (it) * 16; \
        CP_ASYNC16(sbA + (s) * (128 * GP * 4) + (am * GP + ach * 4) * 4, \
                   (const char*)g_wqh + ((size_t)(row0 + am) * CDIM + k0q + ach * 8) * 2); \
        CP_ASYNC16(sbX + (s) * (16 * XP * 4) + (xc * XP + xh) * 4, \
                   (const char*)(Bbase + (size_t)(k0q + xc) * N_PIX + col0 + xh)); \
        CP_COMMIT(); \
    } while (0)

    QKV_CP(0, 0);

    float acc[4][2][4];
#pragma unroll
    for (int mi = 0; mi < 4; mi++)
#pragma unroll
        for (int ni = 0; ni < 2; ni++)
#pragma unroll
            for (int i = 0; i < 4; i++) acc[mi][ni][i] = 0.f;
    float ssp = 0.f;

    for (int it = 0; it < 16; it++) {
        int s = it & 1;
        CP_WAIT0();
        __syncthreads();                  // tile ready; prev MMAs done
        if (it < 15) QKV_CP(it + 1, s ^ 1);
        // stage: f32 [c][p] -> f16 pairs [p][c2] + ssq (via smem)
        {
            const float* xr = &Xf[s][(bc * 4) * XP + bp];
            float v0 = xr[0], v1 = xr[XP], v2 = xr[2 * XP], v3 = xr[3 * XP];
            ssp += v0 * v0 + v1 * v1 + v2 * v2 + v3 * v3;
            uint2 ob;
            ob.x = h2u(__floats2half2_rn(v0, v1));
            ob.y = h2u(__floats2half2_rn(v2, v3));
            *(uint2*)&Bs[s][bp * GP + bc * 2] = ob;
        }
        __syncthreads();                  // Bs ready
        uint32_t af[4][4];
#pragma unroll
        for (int mi = 0; mi < 4; mi++) {
            int r = (wm * 64 + mi * 16 + g) * GP;
            af[mi][0] = As[s][r + tig];
            af[mi][1] = As[s][r + 8 * GP + tig];
            af[mi][2] = As[s][r + tig + 4];
            af[mi][3] = As[s][r + 8 * GP + tig + 4];
        }
#pragma unroll
        for (int ni = 0; ni < 2; ni++) {
            int nb = (wn * 16 + ni * 8 + g) * GP;
            uint32_t b0 = Bs[s][nb + tig];
            uint32_t b1 = Bs[s][nb + tig + 4];
#pragma unroll
            for (int mi = 0; mi < 4; mi++)
                MMA_F16(acc[mi][ni], af[mi], b0, b1);
        }
    }

    ssb[tid] = ssp;
    __syncthreads();

    int t = row0 >> 7;                  // 0=q 1=k 2=v
    float fac = (t == 0) ? (16.f * ATT_SCALE * LOG2E) : 16.f;
    float sc0[2], sc1[2];
#pragma unroll
    for (int ni = 0; ni < 2; ni++) {
        int pp = wn * 16 + ni * 8 + 2 * tig;
        float s0 = ssb[pp] + ssb[pp + 64] + ssb[pp + 128] + ssb[pp + 192];
        float s1 = ssb[pp + 1] + ssb[pp + 65] + ssb[pp + 129] + ssb[pp + 193];
        sc0[ni] = fac / fmaxf(sqrtf(s0), 1e-12f);
        sc1[ni] = fac / fmaxf(sqrtf(s1), 1e-12f);
    }
#pragma unroll
    for (int mi = 0; mi < 4; mi++) {
        int o_lo = row0 + wm * 64 + mi * 16 + g;
        int h = (o_lo >> 5) & 3;
        int f = o_lo & 31;
        size_t hb = (size_t)(b * NH + h);
#pragma unroll
        for (int ni = 0; ni < 2; ni++) {
            int p = col0 + wn * 16 + ni * 8 + 2 * tig;
            float c0 = acc[mi][ni][0] * sc0[ni], c1 = acc[mi][ni][1] * sc1[ni];
            float c2 = acc[mi][ni][2] * sc0[ni], c3 = acc[mi][ni][3] * sc1[ni];
            if (t < 2) {
                __half* d = ((t == 0) ? g_qh : g_kh) + hb * N_PIX * DH;
                d[(size_t)p * DH + f]           = __float2half_rn(c0);
                d[(size_t)(p + 1) * DH + f]     = __float2half_rn(c1);
                d[(size_t)p * DH + f + 8]       = __float2half_rn(c2);
                d[(size_t)(p + 1) * DH + f + 8] = __float2half_rn(c3);
            } else {
                __half* d = g_vh + hb * DH * N_PIX;
                *(__half2*)&d[(size_t)f * N_PIX + p]       = __floats2half2_rn(c0, c1);
                *(__half2*)&d[(size_t)(f + 8) * N_PIX + p] = __floats2half2_rn(c2, c3);
            }
        }
    }
}

// ---------------- kernel 2: flash attention, KV-tile 256 ----------------
#define KPW 20
#define VPW 132
#define KWRD (256 * KPW)          // 5120 words per K buffer
#define VWRD (32 * VPW)           // 4224 words per V buffer
#define SMEM_FLASH ((2 * KWRD + 2 * VWRD) * 4)   // 74752 B

__global__ void __launch_bounds__(256) flash_mma() {
    extern __shared__ uint32_t sm[];
    int tid = threadIdx.x;
    int w   = tid >> 5, lane = tid & 31;
    int g   = lane >> 2, tig = lane & 3;

    int bh = blockIdx.y;
    int r0 = blockIdx.x * 128;
    int qb = r0 + w * 16;

    uint32_t sb = smem_u32(sm);
    const char* khp = (const char*)(g_kh + (size_t)bh * N_PIX * DH);
    const char* vhp = (const char*)(g_vh + (size_t)bh * DH * N_PIX);

    const __half* qp = g_qh + ((size_t)bh * N_PIX + qb) * DH;
    uint32_t qa[2][4];
#pragma unroll
    for (int kt = 0; kt < 2; kt++) {
        int ch = kt * 16 + 2 * tig;
        qa[kt][0] = *(const uint32_t*)&qp[g * DH + ch];
        qa[kt][1] = *(const uint32_t*)&qp[(g + 8) * DH + ch];
        qa[kt][2] = *(const uint32_t*)&qp[g * DH + ch + 8];
        qa[kt][3] = *(const uint32_t*)&qp[(g + 8) * DH + ch + 8];
    }

    float oacc[4][4];
#pragma unroll
    for (int nf = 0; nf < 4; nf++)
#pragma unroll
        for (int i = 0; i < 4; i++) oacc[nf][i] = 0.f;
    float lsum[2] = {0.f, 0.f};

    // stage tile 0: K 256 rows x 64B (1024 chunks) + V 32 rows x 512B (1024 chunks)
#pragma unroll
    for (int i = tid; i < 2048; i += 256) {
        if (i < 1024) {
            int row = i >> 2, cc = i & 3;
            CP_ASYNC16(sb + row * (KPW * 4) + cc * 16, khp + row * 64 + cc * 16);
        } else {
            int j = i - 1024, f = j >> 5, cc = j & 31;
            CP_ASYNC16(sb + 2 * KWRD * 4 + f * (VPW * 4) + cc * 16,
                       vhp + (size_t)f * 8192 + cc * 16);
        }
    }
    CP_COMMIT();

    for (int t = 0; t < 16; t++) {
        // precompute next-tile source pointers before the wait (overlap addr math)
        const char* ks = khp + (size_t)(t + 1) * 16384;   // 256 rows * 64B
        const char* vs = vhp + (size_t)(t + 1) * 512;     // 256 kv * 2B per f-row
        int nb = (t + 1) & 1;
        uint32_t kdst = sb + nb * KWRD * 4;
        uint32_t vdst = sb + (2 * KWRD + nb * VWRD) * 4;

        CP_WAIT0();
        __syncthreads();
        if (t < 15) {
#pragma unroll
            for (int i = tid; i < 2048; i += 256) {
                if (i < 1024) {
                    int row = i >> 2, cc = i & 3;
                    CP_ASYNC16(kdst + row * (KPW * 4) + cc * 16, ks + row * 64 + cc * 16);
                } else {
                    int j = i - 1024, f = j >> 5, cc = j & 31;
                    CP_ASYNC16(vdst + f * (VPW * 4) + cc * 16, vs + (size_t)f * 8192 + cc * 16);
                }
            }
            CP_COMMIT();
        }
        const uint32_t* Ks = sm + (t & 1) * KWRD;
        const uint32_t* Vt = sm + 2 * KWRD + (t & 1) * VWRD;

#pragma unroll
        for (int chk = 0; chk < 8; chk++) {
            float sacc[4][4];
#pragma unroll
            for (int ni = 0; ni < 4; ni++)
#pragma unroll
                for (int i = 0; i < 4; i++) sacc[ni][i] = 0.f;
#pragma unroll
            for (int kt = 0; kt < 2; kt++)
#pragma unroll
                for (int ni = 0; ni < 4; ni++) {
                    int kv = chk * 32 + ni * 8 + g;
                    uint32_t b0 = Ks[kv * KPW + kt * 8 + tig];
                    uint32_t b1 = Ks[kv * KPW + kt * 8 + tig + 4];
                    MMA_F16(sacc[ni], qa[kt], b0, b1);
                }
            // P = 2^S via f16x2 MUFU
            uint32_t pf[4][2];
#pragma unroll
            for (int ni = 0; ni < 4; ni++) {
                pf[ni][0] = ex2_h2(h2u(__floats2half2_rn(sacc[ni][0], sacc[ni][1])));
                pf[ni][1] = ex2_h2(h2u(__floats2half2_rn(sacc[ni][2], sacc[ni][3])));
            }
            // lsum on FMA pipe: depth-2 f16x2 tree, f32 accum
            {
                uint32_t hlo = hadd2u(hadd2u(pf[0][0], pf[1][0]), hadd2u(pf[2][0], pf[3][0]));
                uint32_t hhi = hadd2u(hadd2u(pf[0][1], pf[1][1]), hadd2u(pf[2][1], pf[3][1]));
                float2 flo = __half22float2(*(__half2*)&hlo);
                float2 fhi = __half22float2(*(__half2*)&hhi);
                lsum[0] += flo.x + flo.y;
                lsum[1] += fhi.x + fhi.y;
            }
            // O += P * V^T
#pragma unroll
            for (int kt = 0; kt < 2; kt++) {
                uint32_t pa[4];
                pa[0] = pf[2 * kt][0];
                pa[1] = pf[2 * kt][1];
                pa[2] = pf[2 * kt + 1][0];
                pa[3] = pf[2 * kt + 1][1];
#pragma unroll
                for (int nf = 0; nf < 4; nf++) {
                    int fb = (nf * 8 + g) * VPW + chk * 16 + kt * 8 + tig;
                    uint32_t b0 = Vt[fb];
                    uint32_t b1 = Vt[fb + 4];
                    MMA_F16(oacc[nf], pa, b0, b1);
                }
            }
        }
    }

    float inv[2];
#pragma unroll
    for (int hf = 0; hf < 2; hf++) {
        float v = lsum[hf];
        v += __shfl_xor_sync(0xFFFFFFFF, v, 1);
        v += __shfl_xor_sync(0xFFFFFFFF, v, 2);
        inv[hf] = ATT_SCALE / v;     // second SCALE folded here
    }

    int b = bh >> 2, h = bh & 3;
    __half* ao = g_aoh + (size_t)b * N_PIX * HID + h * DH;
#pragma unroll
    for (int nf = 0; nf < 4; nf++) {
        int f = nf * 8 + 2 * tig;
        int rlo = qb + g, rhi = rlo + 8;
        *(__half2*)&ao[(size_t)rlo * HID + f] =
            __floats2half2_rn(oacc[nf][0] * inv[0], oacc[nf][1] * inv[0]);
        *(__half2*)&ao[(size_t)rhi * HID + f] =
            __floats2half2_rn(oacc[nf][2] * inv[1], oacc[nf][3] * inv[1]);
    }
}

// ---------------- kernel 3: output projection, pure cp.async double-buffer ----------------
__global__ void __launch_bounds__(256) out_mma(const float* __restrict__ bias,
                                               float* __restrict__ out) {
    __shared__ uint32_t As[2][64 * GP];
    __shared__ uint32_t Bs[2][128 * GP];
    int b = blockIdx.z, row0 = blockIdx.y * 64, col0 = blockIdx.x * 128;
    int tid = threadIdx.x, wid = tid >> 5, lane = tid & 31;
    int wm = wid >> 2, wn = wid & 3;
    int g = lane >> 2, tig = lane & 3;
    const char* Bsrc = (const char*)(g_aoh + (size_t)b * N_PIX * HID);

    uint32_t sbA = smem_u32(&As[0][0]);
    uint32_t sbB = smem_u32(&Bs[0][0]);
    int pm = tid >> 1, ch = tid & 1;

#define OUT_CP(it, s) do { \
        int k0q = (it) * 16; \
        if (tid < 128) \
            CP_ASYNC16(sbA + (s) * (64 * GP * 4) + (pm * GP + ch * 4) * 4, \
                       (const char*)g_woh + ((size_t)(row0 + pm) * HID + k0q + ch * 8) * 2); \
        CP_ASYNC16(sbB + (s) * (128 * GP * 4) + (pm * GP + ch * 4) * 4, \
                   Bsrc + ((size_t)(col0 + pm) * HID + k0q + ch * 8) * 2); \
        CP_COMMIT(); \
    } while (0)

    OUT_CP(0, 0);

    float acc[2][4][4];
#pragma unroll
    for (int mi = 0; mi < 2; mi++)
#pragma unroll
        for (int ni = 0; ni < 4; ni++)
#pragma unroll
            for (int i = 0; i < 4; i++) acc[mi][ni][i] = 0.f;

    for (int it = 0; it < 8; it++) {
        int s = it & 1;
        CP_WAIT0();
        __syncthreads();
        if (it < 7) OUT_CP(it + 1, s ^ 1);
        uint32_t af[2][4];
#pragma unroll
        for (int mi = 0; mi < 2; mi++) {
            int r = (wm * 32 + mi * 16 + g) * GP;
            af[mi][0] = As[s][r + tig];
            af[mi][1] = As[s][r + 8 * GP + tig];
            af[mi][2] = As[s][r + tig + 4];
            af[mi][3] = As[s][r + 8 * GP + tig + 4];
        }
#pragma unroll
        for (int ni = 0; ni < 4; ni++) {
            int nb = (wn * 32 + ni * 8 + g) * GP;
            uint32_t b0 = Bs[s][nb + tig];
            uint32_t b1 = Bs[s][nb + tig + 4];
#pragma unroll
            for (int mi = 0; mi < 2; mi++)
                MMA_F16(acc[mi][ni], af[mi], b0, b1);
        }
        __syncthreads();   // MMAs done before next cp overwrites buffer s
    }

#pragma unroll
    for (int mi = 0; mi < 2; mi++) {
        int o_lo = row0 + wm * 32 + mi * 16 + g;
        float b0v = bias[o_lo], b1v = bias[o_lo + 8];
        float* r0p = out + ((size_t)b * CDIM + o_lo) * N_PIX;
        float* r1p = r0p + 8 * N_PIX;
#pragma unroll
        for (int ni = 0; ni < 4; ni++) {
            int p = col0 + wn * 32 + ni * 8 + 2 * tig;
            *(float2*)&r0p[p] = make_float2(acc[mi][ni][0] + b0v, acc[mi][ni][1] + b0v);
            *(float2*)&r1p[p] = make_float2(acc[mi][ni][2] + b1v, acc[mi][ni][3] + b1v);
        }
    }
}

// ---------------- launcher ----------------
extern "C" void kernel_launch(void* const* d_in, const int* in_sizes, int n_in,
                              void* d_out, int out_size) {
    const float* x     = (const float*)d_in[0];
    const float* gvec  = (const float*)d_in[1];
    const float* w_qkv = (const float*)d_in[2];
    const float* w_out = (const float*)d_in[3];
    const float* b_out = (const float*)d_in[4];
    float* out = (float*)d_out;

    static int smem_set = 0;
    if (!smem_set) {
        cudaFuncSetAttribute(flash_mma, cudaFuncAttributeMaxDynamicSharedMemorySize,
                             SMEM_FLASH);
        smem_set = 1;
    }

    prep_w<<<128, 256>>>(w_qkv, gvec, w_out);

    dim3 g1(N_PIX / 64, 3, BATCH);                // 64 x 3 x 2 = 384 CTAs
    qkv_mma<<<g1, 256>>>(x);

    dim3 g2(N_PIX / 128, BATCH * NH);             // 32 x 8
    flash_mma<<<g2, 256, SMEM_FLASH>>>();

    dim3 g3(N_PIX / 128, CDIM / 64, BATCH);       // 32 x 4 x 2
    out_mma<<<g3, 256>>>(b_out, out);
}

// round 14
// speedup vs baseline: 1.0609x; 1.0609x over previous
#include <cuda_runtime.h>
#include <cuda_fp16.h>
#include <math.h>
#include <stdint.h>

#define N_PIX 4096
#define CDIM  256
#define HID   128
#define NH    4
#define DH    32
#define BATCH 2
#define ATT_SCALE 0.17677669529663687f   // 32^-0.5
#define LOG2E     1.4426950408889634f

// ---------------- scratch (static device globals; no allocs) ----------------
__device__ __half g_qh [BATCH * NH * N_PIX * DH];   // [bh][n][f], pre-scaled by ATT_SCALE*LOG2E
__device__ __half g_kh [BATCH * NH * N_PIX * DH];   // [bh][n][f]
__device__ __half g_vh [BATCH * NH * DH * N_PIX];   // [bh][f][n]  (transposed)
__device__ __half g_aoh[BATCH * N_PIX * HID];       // [b][n][h*32+f]  (n-major)
__device__ __half g_wqh[3 * HID * CDIM];            // f16(w_qkv * g)  [o][c]
__device__ __half g_woh[CDIM * HID];                // f16(w_out)      [o][k]
__device__ __half g_xh [BATCH * N_PIX * CDIM];      // f16(x) n-major  [b][p][c]
__device__ float  g_scl[BATCH * N_PIX];             // 16/max(||x||,eps)

__device__ __forceinline__ uint32_t smem_u32(const void* p) {
    uint32_t a;
    asm("{ .reg .u64 t; cvta.to.shared.u64 t, %1; cvt.u32.u64 %0, t; }" : "=r"(a) : "l"(p));
    return a;
}
__device__ __forceinline__ uint32_t h2u(__half2 h) { return *(uint32_t*)&h; }
__device__ __forceinline__ uint32_t ex2_h2(uint32_t x) {
    uint32_t r;
    asm("ex2.approx.f16x2 %0, %1;" : "=r"(r) : "r"(x));
    return r;
}
__device__ __forceinline__ uint32_t hadd2u(uint32_t a, uint32_t b) {
    uint32_t r;
    asm("add.f16x2 %0, %1, %2;" : "=r"(r) : "r"(a), "r"(b));
    return r;
}

#define MMA_F16(c, a, b0_, b1_) \
    asm volatile("mma.sync.aligned.m16n8k16.row.col.f32.f16.f16.f32 " \
        "{%0,%1,%2,%3},{%4,%5,%6,%7},{%8,%9},{%0,%1,%2,%3};" \
        : "+f"((c)[0]), "+f"((c)[1]), "+f"((c)[2]), "+f"((c)[3]) \
        : "r"((a)[0]), "r"((a)[1]), "r"((a)[2]), "r"((a)[3]), "r"(b0_), "r"(b1_))
#define LDSM_X4(r0, r1, r2, r3, addr) \
    asm volatile("ldmatrix.sync.aligned.m8n8.x4.shared.b16 {%0,%1,%2,%3}, [%4];" \
        : "=r"(r0), "=r"(r1), "=r"(r2), "=r"(r3) : "r"(addr))
#define CP_ASYNC16(dst, src) \
    asm volatile("cp.async.ca.shared.global [%0], [%1], 16;" :: "r"(dst), "l"(src))
#define CP_COMMIT() asm volatile("cp.async.commit_group;" ::: "memory")
#define CP_WAIT0()  asm volatile("cp.async.wait_group 0;"  ::: "memory")

// ---------------- kernel 0: prep — weights f16 + x transpose/f16 + norm ----------------
#define XSP 68    // xs pitch in floats (mult of 4 for float4 stores)
__global__ void __launch_bounds__(256) prep(const float* __restrict__ x,
                                            const float* __restrict__ gvec,
                                            const float* __restrict__ wqkv,
                                            const float* __restrict__ wout) {
    int tid = threadIdx.x;
    if (blockIdx.x < 128) {                          // weights
        int i = blockIdx.x * 256 + tid;              // float4 index
        if (i < 24576) {                             // w_qkv: 384*256/4
            float4 wv = ((const float4*)wqkv)[i];
            int c4 = (i & 63) << 2;
            float4 gv = *(const float4*)&gvec[c4];
            uint2 o;
            o.x = h2u(__floats2half2_rn(wv.x * gv.x, wv.y * gv.y));
            o.y = h2u(__floats2half2_rn(wv.z * gv.z, wv.w * gv.w));
            ((uint2*)g_wqh)[i] = o;
        } else {                                     // w_out: 256*128/4
            int j = i - 24576;
            float4 wv = ((const float4*)wout)[j];
            uint2 o;
            o.x = h2u(__floats2half2_rn(wv.x, wv.y));
            o.y = h2u(__floats2half2_rn(wv.z, wv.w));
            ((uint2*)g_woh)[j] = o;
        }
        return;
    }
    // x transpose: 64 pixels per block, all 256 channels
    __shared__ float xs[64 * XSP];                   // [c_local][p]
    __shared__ float ssq[256];
    int bx = blockIdx.x - 128;                       // 0..127
    int pix0 = bx * 64;
    int b = pix0 >> 12, p0 = pix0 & (N_PIX - 1);
    const float* xb = x + (size_t)b * CDIM * N_PIX + p0;
    __half* xh = g_xh + (size_t)(b * N_PIX + p0) * CDIM;

    int q = tid & 3, pw = tid >> 2;                  // write role: pixel pw, c-slice q
    float ssp = 0.f;
    for (int chn = 0; chn < 4; chn++) {
#pragma unroll
        for (int k = 0; k < 4; k++) {                // load 64c x 64p
            int idx = tid + k * 256;
            int r = idx >> 4, c4 = (idx & 15) * 4;
            *(float4*)&xs[r * XSP + c4] =
                *(const float4*)&xb[(size_t)(chn * 64 + r) * N_PIX + c4];
        }
        __syncthreads();
#pragma unroll
        for (int j = 0; j < 8; j++) {                // c pairs (2q+8j, +1)
            int c = 2 * q + 8 * j;
            float a = xs[c * XSP + pw];
            float bb = xs[(c + 1) * XSP + pw];
            ssp += a * a + bb * bb;
            *(__half2*)&xh[(size_t)pw * CDIM + chn * 64 + c] = __floats2half2_rn(a, bb);
        }
        __syncthreads();
    }
    ssq[tid] = ssp;
    __syncthreads();
    if (tid < 64) {
        float s = ssq[tid * 4] + ssq[tid * 4 + 1] + ssq[tid * 4 + 2] + ssq[tid * 4 + 3];
        g_scl[pix0 + tid] = 16.f / fmaxf(sqrtf(s), 1e-12f);
    }
}

// ---------------- kernel 1: QKV GEMM, pure f16 cp.async, 64x128 tiles ----------------
#define GP 12            // f16 smem pitch in uint32 (8 data + 4 pad)
__global__ void __launch_bounds__(256) qkv_mma() {
    __shared__ uint32_t As[2][64 * GP];
    __shared__ uint32_t Bs[2][128 * GP];
    int b = blockIdx.z, row0 = blockIdx.y * 64, col0 = blockIdx.x * 128;
    int tid = threadIdx.x, wid = tid >> 5, lane = tid & 31;
    int wm = wid >> 2, wn = wid & 3;                 // warp = 32m x 32n
    int g = lane >> 2, tig = lane & 3;
    size_t bq = (size_t)b * N_PIX;

    uint32_t sbA = smem_u32(&As[0][0]);
    uint32_t sbB = smem_u32(&Bs[0][0]);
    int pm = tid >> 1, ch = tid & 1;
    // ldsm lane roles
    int lrA = ((lane >> 3) & 1) * 8 + (lane & 7);    // A row-in-16, kw = (lane>>4)*4
    int lkA = (lane >> 4) * 4;
    int lrB = (lane >> 4) * 8 + (lane & 7);          // B row-in-16, kw = ((lane>>3)&1)*4
    int lkB = ((lane >> 3) & 1) * 4;

#define QKV_CP(it_, s_) do { \
        int k0q = (it_) * 16; \
        if (tid < 128) \
            CP_ASYNC16(sbA + (s_) * (64 * GP * 4) + (pm * GP + ch * 4) * 4, \
                       (const char*)g_wqh + ((size_t)(row0 + pm) * CDIM + k0q + ch * 8) * 2); \
        CP_ASYNC16(sbB + (s_) * (128 * GP * 4) + (pm * GP + ch * 4) * 4, \
                   (const char*)g_xh + ((bq + col0 + pm) * CDIM + k0q + ch * 8) * 2); \
        CP_COMMIT(); \
    } while (0)

    QKV_CP(0, 0);

    float acc[2][4][4];
#pragma unroll
    for (int mi = 0; mi < 2; mi++)
#pragma unroll
        for (int ni = 0; ni < 4; ni++)
#pragma unroll
            for (int i = 0; i < 4; i++) acc[mi][ni][i] = 0.f;

    for (int it = 0; it < 16; it++) {
        int s = it & 1;
        CP_WAIT0();
        __syncthreads();
        if (it < 15) QKV_CP(it + 1, s ^ 1);
        uint32_t af[2][4], bf[2][4];
#pragma unroll
        for (int mi = 0; mi < 2; mi++)
            LDSM_X4(af[mi][0], af[mi][1], af[mi][2], af[mi][3],
                    sbA + s * (64 * GP * 4) + ((wm * 32 + mi * 16 + lrA) * GP + lkA) * 4);
#pragma unroll
        for (int pr = 0; pr < 2; pr++)
            LDSM_X4(bf[pr][0], bf[pr][1], bf[pr][2], bf[pr][3],
                    sbB + s * (128 * GP * 4) + ((wn * 32 + pr * 16 + lrB) * GP + lkB) * 4);
#pragma unroll
        for (int ni = 0; ni < 4; ni++) {
            uint32_t b0 = bf[ni >> 1][(ni & 1) * 2];
            uint32_t b1 = bf[ni >> 1][(ni & 1) * 2 + 1];
#pragma unroll
            for (int mi = 0; mi < 2; mi++)
                MMA_F16(acc[mi][ni], af[mi], b0, b1);
        }
        __syncthreads();
    }

    int t = row0 >> 7;                  // 0=q 1=k 2=v
    float fac = (t == 0) ? (ATT_SCALE * LOG2E) : 1.f;
    const float* scl = g_scl + bq;
#pragma unroll
    for (int mi = 0; mi < 2; mi++) {
        int o_lo = row0 + wm * 32 + mi * 16 + g;
        int h = (o_lo >> 5) & 3;
        int f = o_lo & 31;
        size_t hb = (size_t)(b * NH + h);
#pragma unroll
        for (int ni = 0; ni < 4; ni++) {
            int p = col0 + wn * 32 + ni * 8 + 2 * tig;
            float s0 = scl[p] * fac, s1 = scl[p + 1] * fac;
            float c0 = acc[mi][ni][0] * s0, c1 = acc[mi][ni][1] * s1;
            float c2 = acc[mi][ni][2] * s0, c3 = acc[mi][ni][3] * s1;
            if (t < 2) {
                __half* d = ((t == 0) ? g_qh : g_kh) + hb * N_PIX * DH;
                d[(size_t)p * DH + f]           = __float2half_rn(c0);
                d[(size_t)(p + 1) * DH + f]     = __float2half_rn(c1);
                d[(size_t)p * DH + f + 8]       = __float2half_rn(c2);
                d[(size_t)(p + 1) * DH + f + 8] = __float2half_rn(c3);
            } else {
                __half* d = g_vh + hb * DH * N_PIX;
                *(__half2*)&d[(size_t)f * N_PIX + p]       = __floats2half2_rn(c0, c1);
                *(__half2*)&d[(size_t)(f + 8) * N_PIX + p] = __floats2half2_rn(c2, c3);
            }
        }
    }
}

// ---------------- kernel 2: flash attention, ldmatrix fragments ----------------
#define KPW 20
#define VPW 132
#define KWRD (256 * KPW)
#define VWRD (32 * VPW)
#define SMEM_FLASH ((2 * KWRD + 2 * VWRD) * 4)   // 74752 B

__global__ void __launch_bounds__(256) flash_mma() {
    extern __shared__ uint32_t sm[];
    int tid = threadIdx.x;
    int w   = tid >> 5, lane = tid & 31;
    int g   = lane >> 2, tig = lane & 3;
    int rL  = lane & 7, kL = (lane >> 3) * 4;        // ldsm lane roles (K and V)

    int bh = blockIdx.y;
    int r0 = blockIdx.x * 128;
    int qb = r0 + w * 16;

    uint32_t sb = smem_u32(sm);
    const char* khp = (const char*)(g_kh + (size_t)bh * N_PIX * DH);
    const char* vhp = (const char*)(g_vh + (size_t)bh * DH * N_PIX);

    const __half* qp = g_qh + ((size_t)bh * N_PIX + qb) * DH;
    uint32_t qa[2][4];
#pragma unroll
    for (int kt = 0; kt < 2; kt++) {
        int chn = kt * 16 + 2 * tig;
        qa[kt][0] = *(const uint32_t*)&qp[g * DH + chn];
        qa[kt][1] = *(const uint32_t*)&qp[(g + 8) * DH + chn];
        qa[kt][2] = *(const uint32_t*)&qp[g * DH + chn + 8];
        qa[kt][3] = *(const uint32_t*)&qp[(g + 8) * DH + chn + 8];
    }

    float oacc[4][4];
#pragma unroll
    for (int nf = 0; nf < 4; nf++)
#pragma unroll
        for (int i = 0; i < 4; i++) oacc[nf][i] = 0.f;
    float lsum[2] = {0.f, 0.f};

    // stage tile 0: K 256 rows x 64B + V 32 rows x 512B
#pragma unroll
    for (int i = tid; i < 2048; i += 256) {
        if (i < 1024) {
            int row = i >> 2, cc = i & 3;
            CP_ASYNC16(sb + row * (KPW * 4) + cc * 16, khp + row * 64 + cc * 16);
        } else {
            int j = i - 1024, f = j >> 5, cc = j & 31;
            CP_ASYNC16(sb + 2 * KWRD * 4 + f * (VPW * 4) + cc * 16,
                       vhp + (size_t)f * 8192 + cc * 16);
        }
    }
    CP_COMMIT();

    for (int t = 0; t < 16; t++) {
        const char* ks = khp + (size_t)(t + 1) * 16384;
        const char* vs = vhp + (size_t)(t + 1) * 512;
        int nb = (t + 1) & 1;
        uint32_t kdst = sb + nb * KWRD * 4;
        uint32_t vdst = sb + (2 * KWRD + nb * VWRD) * 4;

        CP_WAIT0();
        __syncthreads();
        if (t < 15) {
#pragma unroll
            for (int i = tid; i < 2048; i += 256) {
                if (i < 1024) {
                    int row = i >> 2, cc = i & 3;
                    CP_ASYNC16(kdst + row * (KPW * 4) + cc * 16, ks + row * 64 + cc * 16);
                } else {
                    int j = i - 1024, f = j >> 5, cc = j & 31;
                    CP_ASYNC16(vdst + f * (VPW * 4) + cc * 16, vs + (size_t)f * 8192 + cc * 16);
                }
            }
            CP_COMMIT();
        }
        uint32_t sbK = sb + (t & 1) * (KWRD * 4);
        uint32_t sbV = sb + (2 * KWRD + (t & 1) * VWRD) * 4;

#pragma unroll
        for (int chk = 0; chk < 8; chk++) {
            // fragment loads: 4 ldsm.x4 for K, 4 for V
            uint32_t kf[4][4], vf[4][4];
#pragma unroll
            for (int ni = 0; ni < 4; ni++)
                LDSM_X4(kf[ni][0], kf[ni][1], kf[ni][2], kf[ni][3],
                        sbK + ((chk * 32 + ni * 8 + rL) * KPW + kL) * 4);
#pragma unroll
            for (int nf = 0; nf < 4; nf++)
                LDSM_X4(vf[nf][0], vf[nf][1], vf[nf][2], vf[nf][3],
                        sbV + ((nf * 8 + rL) * VPW + chk * 16 + kL) * 4);
            // S chunk
            float sacc[4][4];
#pragma unroll
            for (int ni = 0; ni < 4; ni++)
#pragma unroll
                for (int i = 0; i < 4; i++) sacc[ni][i] = 0.f;
#pragma unroll
            for (int kt = 0; kt < 2; kt++)
#pragma unroll
                for (int ni = 0; ni < 4; ni++)
                    MMA_F16(sacc[ni], qa[kt], kf[ni][2 * kt], kf[ni][2 * kt + 1]);
            // P = 2^S via f16x2 MUFU
            uint32_t pf[4][2];
#pragma unroll
            for (int ni = 0; ni < 4; ni++) {
                pf[ni][0] = ex2_h2(h2u(__floats2half2_rn(sacc[ni][0], sacc[ni][1])));
                pf[ni][1] = ex2_h2(h2u(__floats2half2_rn(sacc[ni][2], sacc[ni][3])));
            }
            // lsum on FMA pipe
            {
                uint32_t hlo = hadd2u(hadd2u(pf[0][0], pf[1][0]), hadd2u(pf[2][0], pf[3][0]));
                uint32_t hhi = hadd2u(hadd2u(pf[0][1], pf[1][1]), hadd2u(pf[2][1], pf[3][1]));
                float2 flo = __half22float2(*(__half2*)&hlo);
                float2 fhi = __half22float2(*(__half2*)&hhi);
                lsum[0] += flo.x + flo.y;
                lsum[1] += fhi.x + fhi.y;
            }
            // O += P * V^T
#pragma unroll
            for (int kt = 0; kt < 2; kt++) {
                uint32_t pa[4];
                pa[0] = pf[2 * kt][0];
                pa[1] = pf[2 * kt][1];
                pa[2] = pf[2 * kt + 1][0];
                pa[3] = pf[2 * kt + 1][1];
#pragma unroll
                for (int nf = 0; nf < 4; nf++)
                    MMA_F16(oacc[nf], pa, vf[nf][2 * kt], vf[nf][2 * kt + 1]);
            }
        }
    }

    float inv[2];
#pragma unroll
    for (int hf = 0; hf < 2; hf++) {
        float v = lsum[hf];
        v += __shfl_xor_sync(0xFFFFFFFF, v, 1);
        v += __shfl_xor_sync(0xFFFFFFFF, v, 2);
        inv[hf] = ATT_SCALE / v;     // second SCALE folded here
    }

    int b = bh >> 2, h = bh & 3;
    __half* ao = g_aoh + (size_t)b * N_PIX * HID + h * DH;
#pragma unroll
    for (int nf = 0; nf < 4; nf++) {
        int f = nf * 8 + 2 * tig;
        int rlo = qb + g, rhi = rlo + 8;
        *(__half2*)&ao[(size_t)rlo * HID + f] =
            __floats2half2_rn(oacc[nf][0] * inv[0], oacc[nf][1] * inv[0]);
        *(__half2*)&ao[(size_t)rhi * HID + f] =
            __floats2half2_rn(oacc[nf][2] * inv[1], oacc[nf][3] * inv[1]);
    }
}

// ---------------- kernel 3: output projection, cp.async + ldmatrix ----------------
__global__ void __launch_bounds__(256) out_mma(const float* __restrict__ bias,
                                               float* __restrict__ out) {
    __shared__ uint32_t As[2][64 * GP];
    __shared__ uint32_t Bs[2][128 * GP];
    int b = blockIdx.z, row0 = blockIdx.y * 64, col0 = blockIdx.x * 128;
    int tid = threadIdx.x, wid = tid >> 5, lane = tid & 31;
    int wm = wid >> 2, wn = wid & 3;
    int g = lane >> 2, tig = lane & 3;
    const char* Bsrc = (const char*)(g_aoh + (size_t)b * N_PIX * HID);

    uint32_t sbA = smem_u32(&As[0][0]);
    uint32_t sbB = smem_u32(&Bs[0][0]);
    int pm = tid >> 1, ch = tid & 1;
    int lrA = ((lane >> 3) & 1) * 8 + (lane & 7);
    int lkA = (lane >> 4) * 4;
    int lrB = (lane >> 4) * 8 + (lane & 7);
    int lkB = ((lane >> 3) & 1) * 4;

#define OUT_CP(it_, s_) do { \
        int k0q = (it_) * 16; \
        if (tid < 128) \
            CP_ASYNC16(sbA + (s_) * (64 * GP * 4) + (pm * GP + ch * 4) * 4, \
                       (const char*)g_woh + ((size_t)(row0 + pm) * HID + k0q + ch * 8) * 2); \
        CP_ASYNC16(sbB + (s_) * (128 * GP * 4) + (pm * GP + ch * 4) * 4, \
                   Bsrc + ((size_t)(col0 + pm) * HID + k0q + ch * 8) * 2); \
        CP_COMMIT(); \
    } while (0)

    OUT_CP(0, 0);

    float acc[2][4][4];
#pragma unroll
    for (int mi = 0; mi < 2; mi++)
#pragma unroll
        for (int ni = 0; ni < 4; ni++)
#pragma unroll
            for (int i = 0; i < 4; i++) acc[mi][ni][i] = 0.f;

    for (int it = 0; it < 8; it++) {
        int s = it & 1;
        CP_WAIT0();
        __syncthreads();
        if (it < 7) OUT_CP(it + 1, s ^ 1);
        uint32_t af[2][4], bf[2][4];
#pragma unroll
        for (int mi = 0; mi < 2; mi++)
            LDSM_X4(af[mi][0], af[mi][1], af[mi][2], af[mi][3],
                    sbA + s * (64 * GP * 4) + ((wm * 32 + mi * 16 + lrA) * GP + lkA) * 4);
#pragma unroll
        for (int pr = 0; pr < 2; pr++)
            LDSM_X4(bf[pr][0], bf[pr][1], bf[pr][2], bf[pr][3],
                    sbB + s * (128 * GP * 4) + ((wn * 32 + pr * 16 + lrB) * GP + lkB) * 4);
#pragma unroll
        for (int ni = 0; ni < 4; ni++) {
            uint32_t b0 = bf[ni >> 1][(ni & 1) * 2];
            uint32_t b1 = bf[ni >> 1][(ni & 1) * 2 + 1];
#pragma unroll
            for (int mi = 0; mi < 2; mi++)
                MMA_F16(acc[mi][ni], af[mi], b0, b1);
        }
        __syncthreads();
    }

#pragma unroll
    for (int mi = 0; mi < 2; mi++) {
        int o_lo = row0 + wm * 32 + mi * 16 + g;
        float b0v = bias[o_lo], b1v = bias[o_lo + 8];
        float* r0p = out + ((size_t)b * CDIM + o_lo) * N_PIX;
        float* r1p = r0p + 8 * N_PIX;
#pragma unroll
        for (int ni = 0; ni < 4; ni++) {
            int p = col0 + wn * 32 + ni * 8 + 2 * tig;
            *(float2*)&r0p[p] = make_float2(acc[mi][ni][0] + b0v, acc[mi][ni][1] + b0v);
            *(float2*)&r1p[p] = make_float2(acc[mi][ni][2] + b1v, acc[mi][ni][3] + b1v);
        }
    }
}

// ---------------- launcher ----------------
extern "C" void kernel_launch(void* const* d_in, const int* in_sizes, int n_in,
                              void* d_out, int out_size) {
    const float* x     = (const float*)d_in[0];
    const float* gvec  = (const float*)d_in[1];
    const float* w_qkv = (const float*)d_in[2];
    const float* w_out = (const float*)d_in[3];
    const float* b_out = (const float*)d_in[4];
    float* out = (float*)d_out;

    static int smem_set = 0;
    if (!smem_set) {
        cudaFuncSetAttribute(flash_mma, cudaFuncAttributeMaxDynamicSharedMemorySize,
                             SMEM_FLASH);
        smem_set = 1;
    }

    prep<<<256, 256>>>(x, gvec, w_qkv, w_out);

    dim3 g1(N_PIX / 128, 6, BATCH);               // 32 x 6 x 2 = 384 CTAs
    qkv_mma<<<g1, 256>>>();

    dim3 g2(N_PIX / 128, BATCH * NH);             // 32 x 8
    flash_mma<<<g2, 256, SMEM_FLASH>>>();

    dim3 g3(N_PIX / 128, CDIM / 64, BATCH);       // 32 x 4 x 2
    out_mma<<<g3, 256>>>(b_out, out);
}

// round 15
// speedup vs baseline: 1.0785x; 1.0165x over previous
#include <cuda_runtime.h>
#include <cuda_fp16.h>
#include <math.h>
#include <stdint.h>

#define N_PIX 4096
#define CDIM  256
#define HID   128
#define NH    4
#define DH    32
#define BATCH 2
#define ATT_SCALE 0.17677669529663687f   // 32^-0.5
#define LOG2E     1.4426950408889634f

// ---------------- scratch (static device globals; no allocs) ----------------
__device__ __half g_qh [BATCH * NH * N_PIX * DH];   // [bh][n][f], pre-scaled by ATT_SCALE*LOG2E
__device__ __half g_kh [BATCH * NH * N_PIX * DH];   // [bh][n][f]
__device__ __half g_vh [BATCH * NH * DH * N_PIX];   // [bh][f][n]  (transposed)
__device__ __half g_aoh[BATCH * N_PIX * HID];       // [b][n][h*32+f]  (n-major)
__device__ __half g_wqh[3 * HID * CDIM];            // f16(w_qkv * g)  [o][c]
__device__ __half g_woh[CDIM * HID];                // f16(w_out)      [o][k]
__device__ __half g_xh [BATCH * N_PIX * CDIM];      // f16(x) n-major  [b][p][c]
__device__ float  g_scl[BATCH * N_PIX];             // 16/max(||x||,eps)

__device__ __forceinline__ uint32_t smem_u32(const void* p) {
    uint32_t a;
    asm("{ .reg .u64 t; cvta.to.shared.u64 t, %1; cvt.u32.u64 %0, t; }" : "=r"(a) : "l"(p));
    return a;
}
__device__ __forceinline__ uint32_t h2u(__half2 h) { return *(uint32_t*)&h; }
__device__ __forceinline__ uint32_t ex2_h2(uint32_t x) {
    uint32_t r;
    asm("ex2.approx.f16x2 %0, %1;" : "=r"(r) : "r"(x));
    return r;
}
__device__ __forceinline__ uint32_t hadd2u(uint32_t a, uint32_t b) {
    uint32_t r;
    asm("add.f16x2 %0, %1, %2;" : "=r"(r) : "r"(a), "r"(b));
    return r;
}

#define MMA_F16(c, a, b0_, b1_) \
    asm volatile("mma.sync.aligned.m16n8k16.row.col.f32.f16.f16.f32 " \
        "{%0,%1,%2,%3},{%4,%5,%6,%7},{%8,%9},{%0,%1,%2,%3};" \
        : "+f"((c)[0]), "+f"((c)[1]), "+f"((c)[2]), "+f"((c)[3]) \
        : "r"((a)[0]), "r"((a)[1]), "r"((a)[2]), "r"((a)[3]), "r"(b0_), "r"(b1_))
#define LDSM_X4(r0, r1, r2, r3, addr) \
    asm volatile("ldmatrix.sync.aligned.m8n8.x4.shared.b16 {%0,%1,%2,%3}, [%4];" \
        : "=r"(r0), "=r"(r1), "=r"(r2), "=r"(r3) : "r"(addr))
#define CP_ASYNC16(dst, src) \
    asm volatile("cp.async.ca.shared.global [%0], [%1], 16;" :: "r"(dst), "l"(src))
#define CP_COMMIT() asm volatile("cp.async.commit_group;" ::: "memory")
#define CP_WAIT0()  asm volatile("cp.async.wait_group 0;"  ::: "memory")
#define CP_WAIT2()  asm volatile("cp.async.wait_group 2;"  ::: "memory")

// ---------------- kernel 0: prep — weights f16 + x transpose/f16 + norm ----------------
#define XSP 68    // xs pitch in floats
__global__ void __launch_bounds__(256) prep(const float* __restrict__ x,
                                            const float* __restrict__ gvec,
                                            const float* __restrict__ wqkv,
                                            const float* __restrict__ wout) {
    int tid = threadIdx.x;
    if (blockIdx.x < 128) {                          // weights
        int i = blockIdx.x * 256 + tid;              // float4 index
        if (i < 24576) {                             // w_qkv: 384*256/4
            float4 wv = ((const float4*)wqkv)[i];
            int c4 = (i & 63) << 2;
            float4 gv = *(const float4*)&gvec[c4];
            uint2 o;
            o.x = h2u(__floats2half2_rn(wv.x * gv.x, wv.y * gv.y));
            o.y = h2u(__floats2half2_rn(wv.z * gv.z, wv.w * gv.w));
            ((uint2*)g_wqh)[i] = o;
        } else {                                     // w_out: 256*128/4
            int j = i - 24576;
            float4 wv = ((const float4*)wout)[j];
            uint2 o;
            o.x = h2u(__floats2half2_rn(wv.x, wv.y));
            o.y = h2u(__floats2half2_rn(wv.z, wv.w));
            ((uint2*)g_woh)[j] = o;
        }
        return;
    }
    // x transpose: 64 pixels per block, all 256 channels
    __shared__ float xs[64 * XSP];                   // [c_local][p]
    __shared__ float ssq[256];
    int bx = blockIdx.x - 128;                       // 0..127
    int pix0 = bx * 64;
    int b = pix0 >> 12, p0 = pix0 & (N_PIX - 1);
    const float* xb = x + (size_t)b * CDIM * N_PIX + p0;
    __half* xh = g_xh + (size_t)(b * N_PIX + p0) * CDIM;

    int q = tid & 3, pw = tid >> 2;
    float ssp = 0.f;
    for (int chn = 0; chn < 4; chn++) {
#pragma unroll
        for (int k = 0; k < 4; k++) {
            int idx = tid + k * 256;
            int r = idx >> 4, c4 = (idx & 15) * 4;
            *(float4*)&xs[r * XSP + c4] =
                *(const float4*)&xb[(size_t)(chn * 64 + r) * N_PIX + c4];
        }
        __syncthreads();
#pragma unroll
        for (int j = 0; j < 8; j++) {
            int c = 2 * q + 8 * j;
            float a = xs[c * XSP + pw];
            float bb = xs[(c + 1) * XSP + pw];
            ssp += a * a + bb * bb;
            *(__half2*)&xh[(size_t)pw * CDIM + chn * 64 + c] = __floats2half2_rn(a, bb);
        }
        __syncthreads();
    }
    ssq[tid] = ssp;
    __syncthreads();
    if (tid < 64) {
        float s = ssq[tid * 4] + ssq[tid * 4 + 1] + ssq[tid * 4 + 2] + ssq[tid * 4 + 3];
        g_scl[pix0 + tid] = 16.f / fmaxf(sqrtf(s), 1e-12f);
    }
}

// ---------------- kernel 1: QKV GEMM, 4-stage cp.async pipeline ----------------
#define GP 12            // f16 smem pitch in uint32 (8 data + 4 pad)
__global__ void __launch_bounds__(256) qkv_mma() {
    __shared__ uint32_t As[4][64 * GP];
    __shared__ uint32_t Bs[4][128 * GP];
    int b = blockIdx.z, row0 = blockIdx.y * 64, col0 = blockIdx.x * 128;
    int tid = threadIdx.x, wid = tid >> 5, lane = tid & 31;
    int wm = wid >> 2, wn = wid & 3;
    int g = lane >> 2, tig = lane & 3;
    size_t bq = (size_t)b * N_PIX;

    uint32_t sbA = smem_u32(&As[0][0]);
    uint32_t sbB = smem_u32(&Bs[0][0]);
    int pm = tid >> 1, ch = tid & 1;
    int lrA = ((lane >> 3) & 1) * 8 + (lane & 7);
    int lkA = (lane >> 4) * 4;
    int lrB = (lane >> 4) * 8 + (lane & 7);
    int lkB = ((lane >> 3) & 1) * 4;

#define QKV_CP(it_, s_) do { \
        int k0q = (it_) * 16; \
        if (tid < 128) \
            CP_ASYNC16(sbA + (s_) * (64 * GP * 4) + (pm * GP + ch * 4) * 4, \
                       (const char*)g_wqh + ((size_t)(row0 + pm) * CDIM + k0q + ch * 8) * 2); \
        CP_ASYNC16(sbB + (s_) * (128 * GP * 4) + (pm * GP + ch * 4) * 4, \
                   (const char*)g_xh + ((bq + col0 + pm) * CDIM + k0q + ch * 8) * 2); \
        CP_COMMIT(); \
    } while (0)

    QKV_CP(0, 0);
    QKV_CP(1, 1);
    QKV_CP(2, 2);

    float acc[2][4][4];
#pragma unroll
    for (int mi = 0; mi < 2; mi++)
#pragma unroll
        for (int ni = 0; ni < 4; ni++)
#pragma unroll
            for (int i = 0; i < 4; i++) acc[mi][ni][i] = 0.f;

    for (int it = 0; it < 16; it++) {
        int s = it & 3;
        CP_WAIT2();                     // tile it complete (2 younger in flight)
        __syncthreads();
        if (it < 13) QKV_CP(it + 3, (it + 3) & 3);
        else CP_COMMIT();               // empty group keeps wait_group counting valid
        uint32_t af[2][4], bf[2][4];
#pragma unroll
        for (int mi = 0; mi < 2; mi++)
            LDSM_X4(af[mi][0], af[mi][1], af[mi][2], af[mi][3],
                    sbA + s * (64 * GP * 4) + ((wm * 32 + mi * 16 + lrA) * GP + lkA) * 4);
#pragma unroll
        for (int pr = 0; pr < 2; pr++)
            LDSM_X4(bf[pr][0], bf[pr][1], bf[pr][2], bf[pr][3],
                    sbB + s * (128 * GP * 4) + ((wn * 32 + pr * 16 + lrB) * GP + lkB) * 4);
#pragma unroll
        for (int ni = 0; ni < 4; ni++) {
            uint32_t b0 = bf[ni >> 1][(ni & 1) * 2];
            uint32_t b1 = bf[ni >> 1][(ni & 1) * 2 + 1];
#pragma unroll
            for (int mi = 0; mi < 2; mi++)
                MMA_F16(acc[mi][ni], af[mi], b0, b1);
        }
    }

    int t = row0 >> 7;                  // 0=q 1=k 2=v
    float fac = (t == 0) ? (ATT_SCALE * LOG2E) : 1.f;
    const float* scl = g_scl + bq;
#pragma unroll
    for (int mi = 0; mi < 2; mi++) {
        int o_lo = row0 + wm * 32 + mi * 16 + g;
        int h = (o_lo >> 5) & 3;
        int f = o_lo & 31;
        size_t hb = (size_t)(b * NH + h);
#pragma unroll
        for (int ni = 0; ni < 4; ni++) {
            int p = col0 + wn * 32 + ni * 8 + 2 * tig;
            float s0 = scl[p] * fac, s1 = scl[p + 1] * fac;
            float c0 = acc[mi][ni][0] * s0, c1 = acc[mi][ni][1] * s1;
            float c2 = acc[mi][ni][2] * s0, c3 = acc[mi][ni][3] * s1;
            if (t < 2) {
                __half* d = ((t == 0) ? g_qh : g_kh) + hb * N_PIX * DH;
                d[(size_t)p * DH + f]           = __float2half_rn(c0);
                d[(size_t)(p + 1) * DH + f]     = __float2half_rn(c1);
                d[(size_t)p * DH + f + 8]       = __float2half_rn(c2);
                d[(size_t)(p + 1) * DH + f + 8] = __float2half_rn(c3);
            } else {
                __half* d = g_vh + hb * DH * N_PIX;
                *(__half2*)&d[(size_t)f * N_PIX + p]       = __floats2half2_rn(c0, c1);
                *(__half2*)&d[(size_t)(f + 8) * N_PIX + p] = __floats2half2_rn(c2, c3);
            }
        }
    }
}

// ---------------- kernel 2: flash attention, ldmatrix fragments ----------------
#define KPW 20
#define VPW 132
#define KWRD (256 * KPW)
#define VWRD (32 * VPW)
#define SMEM_FLASH ((2 * KWRD + 2 * VWRD) * 4)   // 74752 B

__global__ void __launch_bounds__(256) flash_mma() {
    extern __shared__ uint32_t sm[];
    int tid = threadIdx.x;
    int w   = tid >> 5, lane = tid & 31;
    int g   = lane >> 2, tig = lane & 3;
    int rL  = lane & 7, kL = (lane >> 3) * 4;

    int bh = blockIdx.y;
    int r0 = blockIdx.x * 128;
    int qb = r0 + w * 16;

    uint32_t sb = smem_u32(sm);
    const char* khp = (const char*)(g_kh + (size_t)bh * N_PIX * DH);
    const char* vhp = (const char*)(g_vh + (size_t)bh * DH * N_PIX);

    const __half* qp = g_qh + ((size_t)bh * N_PIX + qb) * DH;
    uint32_t qa[2][4];
#pragma unroll
    for (int kt = 0; kt < 2; kt++) {
        int chn = kt * 16 + 2 * tig;
        qa[kt][0] = *(const uint32_t*)&qp[g * DH + chn];
        qa[kt][1] = *(const uint32_t*)&qp[(g + 8) * DH + chn];
        qa[kt][2] = *(const uint32_t*)&qp[g * DH + chn + 8];
        qa[kt][3] = *(const uint32_t*)&qp[(g + 8) * DH + chn + 8];
    }

    float oacc[4][4];
#pragma unroll
    for (int nf = 0; nf < 4; nf++)
#pragma unroll
        for (int i = 0; i < 4; i++) oacc[nf][i] = 0.f;
    float lsum[2] = {0.f, 0.f};

    // stage tile 0
#pragma unroll
    for (int i = tid; i < 2048; i += 256) {
        if (i < 1024) {
            int row = i >> 2, cc = i & 3;
            CP_ASYNC16(sb + row * (KPW * 4) + cc * 16, khp + row * 64 + cc * 16);
        } else {
            int j = i - 1024, f = j >> 5, cc = j & 31;
            CP_ASYNC16(sb + 2 * KWRD * 4 + f * (VPW * 4) + cc * 16,
                       vhp + (size_t)f * 8192 + cc * 16);
        }
    }
    CP_COMMIT();

    for (int t = 0; t < 16; t++) {
        const char* ks = khp + (size_t)(t + 1) * 16384;
        const char* vs = vhp + (size_t)(t + 1) * 512;
        int nb = (t + 1) & 1;
        uint32_t kdst = sb + nb * KWRD * 4;
        uint32_t vdst = sb + (2 * KWRD + nb * VWRD) * 4;

        CP_WAIT0();
        __syncthreads();
        if (t < 15) {
#pragma unroll
            for (int i = tid; i < 2048; i += 256) {
                if (i < 1024) {
                    int row = i >> 2, cc = i & 3;
                    CP_ASYNC16(kdst + row * (KPW * 4) + cc * 16, ks + row * 64 + cc * 16);
                } else {
                    int j = i - 1024, f = j >> 5, cc = j & 31;
                    CP_ASYNC16(vdst + f * (VPW * 4) + cc * 16, vs + (size_t)f * 8192 + cc * 16);
                }
            }
            CP_COMMIT();
        }
        uint32_t sbK = sb + (t & 1) * (KWRD * 4);
        uint32_t sbV = sb + (2 * KWRD + (t & 1) * VWRD) * 4;

#pragma unroll
        for (int chk = 0; chk < 8; chk++) {
            uint32_t kf[4][4], vf[4][4];
#pragma unroll
            for (int ni = 0; ni < 4; ni++)
                LDSM_X4(kf[ni][0], kf[ni][1], kf[ni][2], kf[ni][3],
                        sbK + ((chk * 32 + ni * 8 + rL) * KPW + kL) * 4);
#pragma unroll
            for (int nf = 0; nf < 4; nf++)
                LDSM_X4(vf[nf][0], vf[nf][1], vf[nf][2], vf[nf][3],
                        sbV + ((nf * 8 + rL) * VPW + chk * 16 + kL) * 4);
            float sacc[4][4];
#pragma unroll
            for (int ni = 0; ni < 4; ni++)
#pragma unroll
                for (int i = 0; i < 4; i++) sacc[ni][i] = 0.f;
#pragma unroll
            for (int kt = 0; kt < 2; kt++)
#pragma unroll
                for (int ni = 0; ni < 4; ni++)
                    MMA_F16(sacc[ni], qa[kt], kf[ni][2 * kt], kf[ni][2 * kt + 1]);
            uint32_t pf[4][2];
#pragma unroll
            for (int ni = 0; ni < 4; ni++) {
                pf[ni][0] = ex2_h2(h2u(__floats2half2_rn(sacc[ni][0], sacc[ni][1])));
                pf[ni][1] = ex2_h2(h2u(__floats2half2_rn(sacc[ni][2], sacc[ni][3])));
            }
            {
                uint32_t hlo = hadd2u(hadd2u(pf[0][0], pf[1][0]), hadd2u(pf[2][0], pf[3][0]));
                uint32_t hhi = hadd2u(hadd2u(pf[0][1], pf[1][1]), hadd2u(pf[2][1], pf[3][1]));
                float2 flo = __half22float2(*(__half2*)&hlo);
                float2 fhi = __half22float2(*(__half2*)&hhi);
                lsum[0] += flo.x + flo.y;
                lsum[1] += fhi.x + fhi.y;
            }
#pragma unroll
            for (int kt = 0; kt < 2; kt++) {
                uint32_t pa[4];
                pa[0] = pf[2 * kt][0];
                pa[1] = pf[2 * kt][1];
                pa[2] = pf[2 * kt + 1][0];
                pa[3] = pf[2 * kt + 1][1];
#pragma unroll
                for (int nf = 0; nf < 4; nf++)
                    MMA_F16(oacc[nf], pa, vf[nf][2 * kt], vf[nf][2 * kt + 1]);
            }
        }
    }

    float inv[2];
#pragma unroll
    for (int hf = 0; hf < 2; hf++) {
        float v = lsum[hf];
        v += __shfl_xor_sync(0xFFFFFFFF, v, 1);
        v += __shfl_xor_sync(0xFFFFFFFF, v, 2);
        inv[hf] = ATT_SCALE / v;     // second SCALE folded here
    }

    int b = bh >> 2, h = bh & 3;
    __half* ao = g_aoh + (size_t)b * N_PIX * HID + h * DH;
#pragma unroll
    for (int nf = 0; nf < 4; nf++) {
        int f = nf * 8 + 2 * tig;
        int rlo = qb + g, rhi = rlo + 8;
        *(__half2*)&ao[(size_t)rlo * HID + f] =
            __floats2half2_rn(oacc[nf][0] * inv[0], oacc[nf][1] * inv[0]);
        *(__half2*)&ao[(size_t)rhi * HID + f] =
            __floats2half2_rn(oacc[nf][2] * inv[1], oacc[nf][3] * inv[1]);
    }
}

// ---------------- kernel 3: output projection, 4-stage cp.async pipeline ----------------
__global__ void __launch_bounds__(256) out_mma(const float* __restrict__ bias,
                                               float* __restrict__ out) {
    __shared__ uint32_t As[4][64 * GP];
    __shared__ uint32_t Bs[4][128 * GP];
    int b = blockIdx.z, row0 = blockIdx.y * 64, col0 = blockIdx.x * 128;
    int tid = threadIdx.x, wid = tid >> 5, lane = tid & 31;
    int wm = wid >> 2, wn = wid & 3;
    int g = lane >> 2, tig = lane & 3;
    const char* Bsrc = (const char*)(g_aoh + (size_t)b * N_PIX * HID);

    uint32_t sbA = smem_u32(&As[0][0]);
    uint32_t sbB = smem_u32(&Bs[0][0]);
    int pm = tid >> 1, ch = tid & 1;
    int lrA = ((lane >> 3) & 1) * 8 + (lane & 7);
    int lkA = (lane >> 4) * 4;
    int lrB = (lane >> 4) * 8 + (lane & 7);
    int lkB = ((lane >> 3) & 1) * 4;

#define OUT_CP(it_, s_) do { \
        int k0q = (it_) * 16; \
        if (tid < 128) \
            CP_ASYNC16(sbA + (s_) * (64 * GP * 4) + (pm * GP + ch * 4) * 4, \
                       (const char*)g_woh + ((size_t)(row0 + pm) * HID + k0q + ch * 8) * 2); \
        CP_ASYNC16(sbB + (s_) * (128 * GP * 4) + (pm * GP + ch * 4) * 4, \
                   Bsrc + ((size_t)(col0 + pm) * HID + k0q + ch * 8) * 2); \
        CP_COMMIT(); \
    } while (0)

    OUT_CP(0, 0);
    OUT_CP(1, 1);
    OUT_CP(2, 2);

    float acc[2][4][4];
#pragma unroll
    for (int mi = 0; mi < 2; mi++)
#pragma unroll
        for (int ni = 0; ni < 4; ni++)
#pragma unroll
            for (int i = 0; i < 4; i++) acc[mi][ni][i] = 0.f;

    for (int it = 0; it < 8; it++) {
        int s = it & 3;
        CP_WAIT2();
        __syncthreads();
        if (it < 5) OUT_CP(it + 3, (it + 3) & 3);
        else CP_COMMIT();
        uint32_t af[2][4], bf[2][4];
#pragma unroll
        for (int mi = 0; mi < 2; mi++)
            LDSM_X4(af[mi][0], af[mi][1], af[mi][2], af[mi][3],
                    sbA + s * (64 * GP * 4) + ((wm * 32 + mi * 16 + lrA) * GP + lkA) * 4);
#pragma unroll
        for (int pr = 0; pr < 2; pr++)
            LDSM_X4(bf[pr][0], bf[pr][1], bf[pr][2], bf[pr][3],
                    sbB + s * (128 * GP * 4) + ((wn * 32 + pr * 16 + lrB) * GP + lkB) * 4);
#pragma unroll
        for (int ni = 0; ni < 4; ni++) {
            uint32_t b0 = bf[ni >> 1][(ni & 1) * 2];
            uint32_t b1 = bf[ni >> 1][(ni & 1) * 2 + 1];
#pragma unroll
            for (int mi = 0; mi < 2; mi++)
                MMA_F16(acc[mi][ni], af[mi], b0, b1);
        }
    }

#pragma unroll
    for (int mi = 0; mi < 2; mi++) {
        int o_lo = row0 + wm * 32 + mi * 16 + g;
        float b0v = bias[o_lo], b1v = bias[o_lo + 8];
        float* r0p = out + ((size_t)b * CDIM + o_lo) * N_PIX;
        float* r1p = r0p + 8 * N_PIX;
#pragma unroll
        for (int ni = 0; ni < 4; ni++) {
            int p = col0 + wn * 32 + ni * 8 + 2 * tig;
            *(float2*)&r0p[p] = make_float2(acc[mi][ni][0] + b0v, acc[mi][ni][1] + b0v);
            *(float2*)&r1p[p] = make_float2(acc[mi][ni][2] + b1v, acc[mi][ni][3] + b1v);
        }
    }
}

// ---------------- launcher ----------------
extern "C" void kernel_launch(void* const* d_in, const int* in_sizes, int n_in,
                              void* d_out, int out_size) {
    const float* x     = (const float*)d_in[0];
    const float* gvec  = (const float*)d_in[1];
    const float* w_qkv = (const float*)d_in[2];
    const float* w_out = (const float*)d_in[3];
    const float* b_out = (const float*)d_in[4];
    float* out = (float*)d_out;

    static int smem_set = 0;
    if (!smem_set) {
        cudaFuncSetAttribute(flash_mma, cudaFuncAttributeMaxDynamicSharedMemorySize,
                             SMEM_FLASH);
        smem_set = 1;
    }

    prep<<<256, 256>>>(x, gvec, w_qkv, w_out);

    dim3 g1(N_PIX / 128, 6, BATCH);               // 32 x 6 x 2 = 384 CTAs
    qkv_mma<<<g1, 256>>>();

    dim3 g2(N_PIX / 128, BATCH * NH);             // 32 x 8
    flash_mma<<<g2, 256, SMEM_FLASH>>>();

    dim3 g3(N_PIX / 128, CDIM / 64, BATCH);       // 32 x 4 x 2
    out_mma<<<g3, 256>>>(b_out, out);
}

// round 16
// speedup vs baseline: 1.0825x; 1.0038x over previous
#include <cuda_runtime.h>
#include <cuda_fp16.h>
#include <math.h>
#include <stdint.h>

#define N_PIX 4096
#define CDIM  256
#define HID   128
#define NH    4
#define DH    32
#define BATCH 2
#define ATT_SCALE 0.17677669529663687f   // 32^-0.5
#define LOG2E     1.4426950408889634f
#define GRID_N 256

// ---------------- scratch (static device globals; no allocs) ----------------
__device__ __half g_qh [BATCH * NH * N_PIX * DH];   // [bh][n][f], pre-scaled by ATT_SCALE*LOG2E
__device__ __half g_kh [BATCH * NH * N_PIX * DH];   // [bh][n][f]
__device__ __half g_vh [BATCH * NH * DH * N_PIX];   // [bh][f][n]  (transposed)
__device__ __half g_aoh[BATCH * N_PIX * HID];       // [b][n][h*32+f]  (n-major)
__device__ __half g_wqh[3 * HID * CDIM];            // f16(w_qkv * g)  [o][c]
__device__ __half g_woh[CDIM * HID];                // f16(w_out)      [o][k]
__device__ __half g_xh [BATCH * N_PIX * CDIM];      // f16(x) n-major  [b][p][c]
__device__ float  g_scl[BATCH * N_PIX];             // 16/max(||x||,eps)
__device__ unsigned g_count = 0;                    // barrier arrivals (self-resetting)
__device__ unsigned g_gen   = 0;                    // barrier generation (monotonic)

__device__ __forceinline__ uint32_t smem_u32(const void* p) {
    uint32_t a;
    asm("{ .reg .u64 t; cvta.to.shared.u64 t, %1; cvt.u32.u64 %0, t; }" : "=r"(a) : "l"(p));
    return a;
}
__device__ __forceinline__ uint32_t h2u(__half2 h) { return *(uint32_t*)&h; }
__device__ __forceinline__ uint32_t ex2_h2(uint32_t x) {
    uint32_t r;
    asm("ex2.approx.f16x2 %0, %1;" : "=r"(r) : "r"(x));
    return r;
}
__device__ __forceinline__ uint32_t hadd2u(uint32_t a, uint32_t b) {
    uint32_t r;
    asm("add.f16x2 %0, %1, %2;" : "=r"(r) : "r"(a), "r"(b));
    return r;
}
// All-resident grid barrier (2 CTAs/SM guaranteed by launch_bounds+smem => 256<=296 co-resident)
__device__ __forceinline__ void grid_barrier() {
    __syncthreads();
    if (threadIdx.x == 0) {
        unsigned gen = *((volatile unsigned*)&g_gen);
        __threadfence();
        if (atomicAdd(&g_count, 1) == GRID_N - 1) {
            atomicExch(&g_count, 0);
            __threadfence();
            atomicAdd(&g_gen, 1);
        } else {
            while (*((volatile unsigned*)&g_gen) == gen) {}
        }
        __threadfence();
    }
    __syncthreads();
}

#define MMA_F16(c, a, b0_, b1_) \
    asm volatile("mma.sync.aligned.m16n8k16.row.col.f32.f16.f16.f32 " \
        "{%0,%1,%2,%3},{%4,%5,%6,%7},{%8,%9},{%0,%1,%2,%3};" \
        : "+f"((c)[0]), "+f"((c)[1]), "+f"((c)[2]), "+f"((c)[3]) \
        : "r"((a)[0]), "r"((a)[1]), "r"((a)[2]), "r"((a)[3]), "r"(b0_), "r"(b1_))
#define LDSM_X4(r0, r1, r2, r3, addr) \
    asm volatile("ldmatrix.sync.aligned.m8n8.x4.shared.b16 {%0,%1,%2,%3}, [%4];" \
        : "=r"(r0), "=r"(r1), "=r"(r2), "=r"(r3) : "r"(addr))
#define CP_ASYNC16(dst, src) \
    asm volatile("cp.async.ca.shared.global [%0], [%1], 16;" :: "r"(dst), "l"(src))
#define CP_COMMIT() asm volatile("cp.async.commit_group;" ::: "memory")
#define CP_WAIT0()  asm volatile("cp.async.wait_group 0;"  ::: "memory")
#define CP_WAIT2()  asm volatile("cp.async.wait_group 2;"  ::: "memory")

#define GP  12           // f16 smem pitch in uint32
#define XSP 68           // prep staging pitch in floats
#define KPW 20
#define VPW 132
#define KWRD (256 * KPW)
#define VWRD (32 * VPW)
#define SMEM_BYTES ((2 * KWRD + 2 * VWRD) * 4)   // 74752 (max over phases)

__global__ void __launch_bounds__(256, 2) fused(const float* __restrict__ x,
                                                const float* __restrict__ gvec,
                                                const float* __restrict__ wqkv,
                                                const float* __restrict__ wout,
                                                const float* __restrict__ bias,
                                                float* __restrict__ out) {
    extern __shared__ uint32_t sm[];
    int bid = blockIdx.x;
    int tid = threadIdx.x, wid = tid >> 5, lane = tid & 31;
    int g = lane >> 2, tig = lane & 3;

    // ================= phase 1: prep (weights f16 / x transpose + norm) =================
    if (bid < 128) {
        int i = bid * 256 + tid;
        if (i < 24576) {
            float4 wv = ((const float4*)wqkv)[i];
            int c4 = (i & 63) << 2;
            float4 gv = *(const float4*)&gvec[c4];
            uint2 o;
            o.x = h2u(__floats2half2_rn(wv.x * gv.x, wv.y * gv.y));
            o.y = h2u(__floats2half2_rn(wv.z * gv.z, wv.w * gv.w));
            ((uint2*)g_wqh)[i] = o;
        } else {
            int j = i - 24576;
            float4 wv = ((const float4*)wout)[j];
            uint2 o;
            o.x = h2u(__floats2half2_rn(wv.x, wv.y));
            o.y = h2u(__floats2half2_rn(wv.z, wv.w));
            ((uint2*)g_woh)[j] = o;
        }
    } else {
        float* xs  = (float*)sm;
        float* ssq = xs + 64 * XSP;
        int pix0 = (bid - 128) * 64;
        int b = pix0 >> 12, p0 = pix0 & (N_PIX - 1);
        const float* xb = x + (size_t)b * CDIM * N_PIX + p0;
        __half* xh = g_xh + (size_t)(b * N_PIX + p0) * CDIM;
        int q = tid & 3, pw = tid >> 2;
        float ssp = 0.f;
        for (int chn = 0; chn < 4; chn++) {
#pragma unroll
            for (int k = 0; k < 4; k++) {
                int idx = tid + k * 256;
                int r = idx >> 4, c4 = (idx & 15) * 4;
                *(float4*)&xs[r * XSP + c4] =
                    *(const float4*)&xb[(size_t)(chn * 64 + r) * N_PIX + c4];
            }
            __syncthreads();
#pragma unroll
            for (int j = 0; j < 8; j++) {
                int c = 2 * q + 8 * j;
                float a = xs[c * XSP + pw];
                float bb = xs[(c + 1) * XSP + pw];
                ssp += a * a + bb * bb;
                *(__half2*)&xh[(size_t)pw * CDIM + chn * 64 + c] = __floats2half2_rn(a, bb);
            }
            __syncthreads();
        }
        ssq[tid] = ssp;
        __syncthreads();
        if (tid < 64) {
            float s = ssq[tid * 4] + ssq[tid * 4 + 1] + ssq[tid * 4 + 2] + ssq[tid * 4 + 3];
            g_scl[pix0 + tid] = 16.f / fmaxf(sqrtf(s), 1e-12f);
        }
    }
    grid_barrier();

    // ================= phase 2: QKV GEMM (384 items over 256 CTAs) =================
    {
        uint32_t* As = sm;                     // [4][64*GP]
        uint32_t* Bs = sm + 4 * 64 * GP;       // [4][128*GP]
        uint32_t sbA = smem_u32(As);
        uint32_t sbB = smem_u32(Bs);
        int pm = tid >> 1, ch = tid & 1;
        int wm = wid >> 2, wn = wid & 3;
        int lrA = ((lane >> 3) & 1) * 8 + (lane & 7);
        int lkA = (lane >> 4) * 4;
        int lrB = (lane >> 4) * 8 + (lane & 7);
        int lkB = ((lane >> 3) & 1) * 4;

        for (int item = bid; item < 384; item += GRID_N) {
            int b = item / 192, rem = item % 192;
            int row0 = (rem >> 5) * 64, col0 = (rem & 31) * 128;
            size_t bq = (size_t)b * N_PIX;
            __syncthreads();               // all warps done with smem before rewrite

#define QKV_CP(it_, s_) do { \
        int k0q = (it_) * 16; \
        if (tid < 128) \
            CP_ASYNC16(sbA + (s_) * (64 * GP * 4) + (pm * GP + ch * 4) * 4, \
                       (const char*)g_wqh + ((size_t)(row0 + pm) * CDIM + k0q + ch * 8) * 2); \
        CP_ASYNC16(sbB + (s_) * (128 * GP * 4) + (pm * GP + ch * 4) * 4, \
                   (const char*)g_xh + ((bq + col0 + pm) * CDIM + k0q + ch * 8) * 2); \
        CP_COMMIT(); \
    } while (0)

            QKV_CP(0, 0);
            QKV_CP(1, 1);
            QKV_CP(2, 2);

            float acc[2][4][4];
#pragma unroll
            for (int mi = 0; mi < 2; mi++)
#pragma unroll
                for (int ni = 0; ni < 4; ni++)
#pragma unroll
                    for (int i = 0; i < 4; i++) acc[mi][ni][i] = 0.f;

            for (int it = 0; it < 16; it++) {
                int s = it & 3;
                CP_WAIT2();
                __syncthreads();
                if (it < 13) QKV_CP(it + 3, (it + 3) & 3);
                else CP_COMMIT();
                uint32_t af[2][4], bf[2][4];
#pragma unroll
                for (int mi = 0; mi < 2; mi++)
                    LDSM_X4(af[mi][0], af[mi][1], af[mi][2], af[mi][3],
                            sbA + s * (64 * GP * 4) + ((wm * 32 + mi * 16 + lrA) * GP + lkA) * 4);
#pragma unroll
                for (int pr = 0; pr < 2; pr++)
                    LDSM_X4(bf[pr][0], bf[pr][1], bf[pr][2], bf[pr][3],
                            sbB + s * (128 * GP * 4) + ((wn * 32 + pr * 16 + lrB) * GP + lkB) * 4);
#pragma unroll
                for (int ni = 0; ni < 4; ni++) {
                    uint32_t b0 = bf[ni >> 1][(ni & 1) * 2];
                    uint32_t b1 = bf[ni >> 1][(ni & 1) * 2 + 1];
#pragma unroll
                    for (int mi = 0; mi < 2; mi++)
                        MMA_F16(acc[mi][ni], af[mi], b0, b1);
                }
            }
            CP_WAIT0();

            int t = row0 >> 7;
            float fac = (t == 0) ? (ATT_SCALE * LOG2E) : 1.f;
            const float* scl = g_scl + bq;
#pragma unroll
            for (int mi = 0; mi < 2; mi++) {
                int o_lo = row0 + wm * 32 + mi * 16 + g;
                int h = (o_lo >> 5) & 3;
                int f = o_lo & 31;
                size_t hb = (size_t)(b * NH + h);
#pragma unroll
                for (int ni = 0; ni < 4; ni++) {
                    int p = col0 + wn * 32 + ni * 8 + 2 * tig;
                    float s0 = scl[p] * fac, s1 = scl[p + 1] * fac;
                    float c0 = acc[mi][ni][0] * s0, c1 = acc[mi][ni][1] * s1;
                    float c2 = acc[mi][ni][2] * s0, c3 = acc[mi][ni][3] * s1;
                    if (t < 2) {
                        __half* d = ((t == 0) ? g_qh : g_kh) + hb * N_PIX * DH;
                        d[(size_t)p * DH + f]           = __float2half_rn(c0);
                        d[(size_t)(p + 1) * DH + f]     = __float2half_rn(c1);
                        d[(size_t)p * DH + f + 8]       = __float2half_rn(c2);
                        d[(size_t)(p + 1) * DH + f + 8] = __float2half_rn(c3);
                    } else {
                        __half* d = g_vh + hb * DH * N_PIX;
                        *(__half2*)&d[(size_t)f * N_PIX + p]       = __floats2half2_rn(c0, c1);
                        *(__half2*)&d[(size_t)(f + 8) * N_PIX + p] = __floats2half2_rn(c2, c3);
                    }
                }
            }
        }
    }
    grid_barrier();

    // ================= phase 3: flash attention (256 items) =================
    {
        int rL = lane & 7, kL = (lane >> 3) * 4;
        int bh = bid >> 5;
        int r0 = (bid & 31) * 128;
        int w = wid;
        int qb = r0 + w * 16;

        uint32_t sb = smem_u32(sm);
        const char* khp = (const char*)(g_kh + (size_t)bh * N_PIX * DH);
        const char* vhp = (const char*)(g_vh + (size_t)bh * DH * N_PIX);

        const __half* qp = g_qh + ((size_t)bh * N_PIX + qb) * DH;
        uint32_t qa[2][4];
#pragma unroll
        for (int kt = 0; kt < 2; kt++) {
            int chn = kt * 16 + 2 * tig;
            qa[kt][0] = *(const uint32_t*)&qp[g * DH + chn];
            qa[kt][1] = *(const uint32_t*)&qp[(g + 8) * DH + chn];
            qa[kt][2] = *(const uint32_t*)&qp[g * DH + chn + 8];
            qa[kt][3] = *(const uint32_t*)&qp[(g + 8) * DH + chn + 8];
        }

        float oacc[4][4];
#pragma unroll
        for (int nf = 0; nf < 4; nf++)
#pragma unroll
            for (int i = 0; i < 4; i++) oacc[nf][i] = 0.f;
        float lsum[2] = {0.f, 0.f};

#pragma unroll
        for (int i = tid; i < 2048; i += 256) {
            if (i < 1024) {
                int row = i >> 2, cc = i & 3;
                CP_ASYNC16(sb + row * (KPW * 4) + cc * 16, khp + row * 64 + cc * 16);
            } else {
                int j = i - 1024, f = j >> 5, cc = j & 31;
                CP_ASYNC16(sb + 2 * KWRD * 4 + f * (VPW * 4) + cc * 16,
                           vhp + (size_t)f * 8192 + cc * 16);
            }
        }
        CP_COMMIT();

        for (int t = 0; t < 16; t++) {
            const char* ks = khp + (size_t)(t + 1) * 16384;
            const char* vs = vhp + (size_t)(t + 1) * 512;
            int nb = (t + 1) & 1;
            uint32_t kdst = sb + nb * KWRD * 4;
            uint32_t vdst = sb + (2 * KWRD + nb * VWRD) * 4;

            CP_WAIT0();
            __syncthreads();
            if (t < 15) {
#pragma unroll
                for (int i = tid; i < 2048; i += 256) {
                    if (i < 1024) {
                        int row = i >> 2, cc = i & 3;
                        CP_ASYNC16(kdst + row * (KPW * 4) + cc * 16, ks + row * 64 + cc * 16);
                    } else {
                        int j = i - 1024, f = j >> 5, cc = j & 31;
                        CP_ASYNC16(vdst + f * (VPW * 4) + cc * 16, vs + (size_t)f * 8192 + cc * 16);
                    }
                }
                CP_COMMIT();
            }
            uint32_t sbK = sb + (t & 1) * (KWRD * 4);
            uint32_t sbV = sb + (2 * KWRD + (t & 1) * VWRD) * 4;

#pragma unroll
            for (int chk = 0; chk < 8; chk++) {
                uint32_t kf[4][4], vf[4][4];
#pragma unroll
                for (int ni = 0; ni < 4; ni++)
                    LDSM_X4(kf[ni][0], kf[ni][1], kf[ni][2], kf[ni][3],
                            sbK + ((chk * 32 + ni * 8 + rL) * KPW + kL) * 4);
#pragma unroll
                for (int nf = 0; nf < 4; nf++)
                    LDSM_X4(vf[nf][0], vf[nf][1], vf[nf][2], vf[nf][3],
                            sbV + ((nf * 8 + rL) * VPW + chk * 16 + kL) * 4);
                float sacc[4][4];
#pragma unroll
                for (int ni = 0; ni < 4; ni++)
#pragma unroll
                    for (int i = 0; i < 4; i++) sacc[ni][i] = 0.f;
#pragma unroll
                for (int kt = 0; kt < 2; kt++)
#pragma unroll
                    for (int ni = 0; ni < 4; ni++)
                        MMA_F16(sacc[ni], qa[kt], kf[ni][2 * kt], kf[ni][2 * kt + 1]);
                uint32_t pf[4][2];
#pragma unroll
                for (int ni = 0; ni < 4; ni++) {
                    pf[ni][0] = ex2_h2(h2u(__floats2half2_rn(sacc[ni][0], sacc[ni][1])));
                    pf[ni][1] = ex2_h2(h2u(__floats2half2_rn(sacc[ni][2], sacc[ni][3])));
                }
                {
                    uint32_t hlo = hadd2u(hadd2u(pf[0][0], pf[1][0]), hadd2u(pf[2][0], pf[3][0]));
                    uint32_t hhi = hadd2u(hadd2u(pf[0][1], pf[1][1]), hadd2u(pf[2][1], pf[3][1]));
                    float2 flo = __half22float2(*(__half2*)&hlo);
                    float2 fhi = __half22float2(*(__half2*)&hhi);
                    lsum[0] += flo.x + flo.y;
                    lsum[1] += fhi.x + fhi.y;
                }
#pragma unroll
                for (int kt = 0; kt < 2; kt++) {
                    uint32_t pa[4];
                    pa[0] = pf[2 * kt][0];
                    pa[1] = pf[2 * kt][1];
                    pa[2] = pf[2 * kt + 1][0];
                    pa[3] = pf[2 * kt + 1][1];
#pragma unroll
                    for (int nf = 0; nf < 4; nf++)
                        MMA_F16(oacc[nf], pa, vf[nf][2 * kt], vf[nf][2 * kt + 1]);
                }
            }
        }

        float inv[2];
#pragma unroll
        for (int hf = 0; hf < 2; hf++) {
            float v = lsum[hf];
            v += __shfl_xor_sync(0xFFFFFFFF, v, 1);
            v += __shfl_xor_sync(0xFFFFFFFF, v, 2);
            inv[hf] = ATT_SCALE / v;
        }

        int b = bh >> 2, h = bh & 3;
        __half* ao = g_aoh + (size_t)b * N_PIX * HID + h * DH;
#pragma unroll
        for (int nf = 0; nf < 4; nf++) {
            int f = nf * 8 + 2 * tig;
            int rlo = qb + g, rhi = rlo + 8;
            *(__half2*)&ao[(size_t)rlo * HID + f] =
                __floats2half2_rn(oacc[nf][0] * inv[0], oacc[nf][1] * inv[0]);
            *(__half2*)&ao[(size_t)rhi * HID + f] =
                __floats2half2_rn(oacc[nf][2] * inv[1], oacc[nf][3] * inv[1]);
        }
    }
    grid_barrier();

    // ================= phase 4: output projection (256 items) =================
    {
        uint32_t* As = sm;
        uint32_t* Bs = sm + 4 * 64 * GP;
        uint32_t sbA = smem_u32(As);
        uint32_t sbB = smem_u32(Bs);
        int pm = tid >> 1, ch = tid & 1;
        int wm = wid >> 2, wn = wid & 3;
        int lrA = ((lane >> 3) & 1) * 8 + (lane & 7);
        int lkA = (lane >> 4) * 4;
        int lrB = (lane >> 4) * 8 + (lane & 7);
        int lkB = ((lane >> 3) & 1) * 4;

        int b = bid >> 7, rem = bid & 127;
        int row0 = (rem >> 5) * 64, col0 = (rem & 31) * 128;
        const char* Bsrc = (const char*)(g_aoh + (size_t)b * N_PIX * HID);

#define OUT_CP(it_, s_) do { \
        int k0q = (it_) * 16; \
        if (tid < 128) \
            CP_ASYNC16(sbA + (s_) * (64 * GP * 4) + (pm * GP + ch * 4) * 4, \
                       (const char*)g_woh + ((size_t)(row0 + pm) * HID + k0q + ch * 8) * 2); \
        CP_ASYNC16(sbB + (s_) * (128 * GP * 4) + (pm * GP + ch * 4) * 4, \
                   Bsrc + ((size_t)(col0 + pm) * HID + k0q + ch * 8) * 2); \
        CP_COMMIT(); \
    } while (0)

        OUT_CP(0, 0);
        OUT_CP(1, 1);
        OUT_CP(2, 2);

        float acc[2][4][4];
#pragma unroll
        for (int mi = 0; mi < 2; mi++)
#pragma unroll
            for (int ni = 0; ni < 4; ni++)
#pragma unroll
                for (int i = 0; i < 4; i++) acc[mi][ni][i] = 0.f;

        for (int it = 0; it < 8; it++) {
            int s = it & 3;
            CP_WAIT2();
            __syncthreads();
            if (it < 5) OUT_CP(it + 3, (it + 3) & 3);
            else CP_COMMIT();
            uint32_t af[2][4], bf[2][4];
#pragma unroll
            for (int mi = 0; mi < 2; mi++)
                LDSM_X4(af[mi][0], af[mi][1], af[mi][2], af[mi][3],
                        sbA + s * (64 * GP * 4) + ((wm * 32 + mi * 16 + lrA) * GP + lkA) * 4);
#pragma unroll
            for (int pr = 0; pr < 2; pr++)
                LDSM_X4(bf[pr][0], bf[pr][1], bf[pr][2], bf[pr][3],
                        sbB + s * (128 * GP * 4) + ((wn * 32 + pr * 16 + lrB) * GP + lkB) * 4);
#pragma unroll
            for (int ni = 0; ni < 4; ni++) {
                uint32_t b0 = bf[ni >> 1][(ni & 1) * 2];
                uint32_t b1 = bf[ni >> 1][(ni & 1) * 2 + 1];
#pragma unroll
                for (int mi = 0; mi < 2; mi++)
                    MMA_F16(acc[mi][ni], af[mi], b0, b1);
            }
        }
        CP_WAIT0();

#pragma unroll
        for (int mi = 0; mi < 2; mi++) {
            int o_lo = row0 + wm * 32 + mi * 16 + g;
            float b0v = bias[o_lo], b1v = bias[o_lo + 8];
            float* r0p = out + ((size_t)b * CDIM + o_lo) * N_PIX;
            float* r1p = r0p + 8 * N_PIX;
#pragma unroll
            for (int ni = 0; ni < 4; ni++) {
                int p = col0 + wn * 32 + ni * 8 + 2 * tig;
                *(float2*)&r0p[p] = make_float2(acc[mi][ni][0] + b0v, acc[mi][ni][1] + b0v);
                *(float2*)&r1p[p] = make_float2(acc[mi][ni][2] + b1v, acc[mi][ni][3] + b1v);
            }
        }
    }
}

// ---------------- launcher ----------------
extern "C" void kernel_launch(void* const* d_in, const int* in_sizes, int n_in,
                              void* d_out, int out_size) {
    const float* x     = (const float*)d_in[0];
    const float* gvec  = (const float*)d_in[1];
    const float* w_qkv = (const float*)d_in[2];
    const float* w_out = (const float*)d_in[3];
    const float* b_out = (const float*)d_in[4];
    float* out = (float*)d_out;

    static int smem_set = 0;
    if (!smem_set) {
        cudaFuncSetAttribute(fused, cudaFuncAttributeMaxDynamicSharedMemorySize,
                             SMEM_BYTES);
        smem_set = 1;
    }

    fused<<<GRID_N, 256, SMEM_BYTES>>>(x, gvec, w_qkv, w_out, b_out, out);
}

// round 17
// speedup vs baseline: 1.1659x; 1.0771x over previous
#include <cuda_runtime.h>
#include <cuda_fp16.h>
#include <math.h>
#include <stdint.h>

#define N_PIX 4096
#define CDIM  256
#define HID   128
#define NH    4
#define DH    32
#define BATCH 2
#define ATT_SCALE 0.17677669529663687f   // 32^-0.5
#define LOG2E     1.4426950408889634f
#define GRID_N 256
#define ONES_H2 0x3C003C00u              // f16x2 (1.0, 1.0)

// ---------------- scratch (static device globals; no allocs) ----------------
__device__ __half g_qh [BATCH * NH * N_PIX * DH];   // [bh][n][f], pre-scaled by ATT_SCALE*LOG2E
__device__ __half g_kh [BATCH * NH * N_PIX * DH];   // [bh][n][f]
__device__ __half g_vh [BATCH * NH * DH * N_PIX];   // [bh][f][n]  (transposed)
__device__ __half g_aoh[BATCH * N_PIX * HID];       // [b][n][h*32+f]  (n-major)
__device__ __half g_wqh[3 * HID * CDIM];            // f16(w_qkv * g)  [o][c]
__device__ __half g_woh[CDIM * HID];                // f16(w_out)      [o][k]
__device__ __half g_xh [BATCH * N_PIX * CDIM];      // f16(x) n-major  [b][p][c]
__device__ float  g_scl[BATCH * N_PIX];             // 16/max(||x||,eps)
__device__ unsigned g_count = 0;                    // barrier arrivals (self-resetting)
__device__ unsigned g_gen   = 0;                    // barrier generation (monotonic)

__device__ __forceinline__ uint32_t smem_u32(const void* p) {
    uint32_t a;
    asm("{ .reg .u64 t; cvta.to.shared.u64 t, %1; cvt.u32.u64 %0, t; }" : "=r"(a) : "l"(p));
    return a;
}
__device__ __forceinline__ uint32_t h2u(__half2 h) { return *(uint32_t*)&h; }
__device__ __forceinline__ uint32_t ex2_h2(uint32_t x) {
    uint32_t r;
    asm("ex2.approx.f16x2 %0, %1;" : "=r"(r) : "r"(x));
    return r;
}
// All-resident grid barrier (2 CTAs/SM guaranteed => 256 <= 296 co-resident)
__device__ __forceinline__ void grid_barrier() {
    __syncthreads();
    if (threadIdx.x == 0) {
        unsigned gen = *((volatile unsigned*)&g_gen);
        __threadfence();
        if (atomicAdd(&g_count, 1) == GRID_N - 1) {
            atomicExch(&g_count, 0);
            __threadfence();
            atomicAdd(&g_gen, 1);
        } else {
            while (*((volatile unsigned*)&g_gen) == gen) {}
        }
        __threadfence();
    }
    __syncthreads();
}

#define MMA_F16(c, a, b0_, b1_) \
    asm volatile("mma.sync.aligned.m16n8k16.row.col.f32.f16.f16.f32 " \
        "{%0,%1,%2,%3},{%4,%5,%6,%7},{%8,%9},{%0,%1,%2,%3};" \
        : "+f"((c)[0]), "+f"((c)[1]), "+f"((c)[2]), "+f"((c)[3]) \
        : "r"((a)[0]), "r"((a)[1]), "r"((a)[2]), "r"((a)[3]), "r"(b0_), "r"(b1_))
#define LDSM_X4(r0, r1, r2, r3, addr) \
    asm volatile("ldmatrix.sync.aligned.m8n8.x4.shared.b16 {%0,%1,%2,%3}, [%4];" \
        : "=r"(r0), "=r"(r1), "=r"(r2), "=r"(r3) : "r"(addr))
#define CP_ASYNC16(dst, src) \
    asm volatile("cp.async.ca.shared.global [%0], [%1], 16;" :: "r"(dst), "l"(src))
#define CP_COMMIT() asm volatile("cp.async.commit_group;" ::: "memory")
#define CP_WAIT0()  asm volatile("cp.async.wait_group 0;"  ::: "memory")
#define CP_WAIT2()  asm volatile("cp.async.wait_group 2;"  ::: "memory")

#define GP  12           // f16 smem pitch in uint32
#define XSP 68           // prep staging pitch in floats
#define KPW 20
#define VPW 132
#define KWRD (256 * KPW)
#define VWRD (32 * VPW)
#define SMEM_BYTES ((2 * KWRD + 2 * VWRD) * 4)   // 74752 (max over phases)

__global__ void __launch_bounds__(256, 2) fused(const float* __restrict__ x,
                                                const float* __restrict__ gvec,
                                                const float* __restrict__ wqkv,
                                                const float* __restrict__ wout,
                                                const float* __restrict__ bias,
                                                float* __restrict__ out) {
    extern __shared__ uint32_t sm[];
    int bid = blockIdx.x;
    int tid = threadIdx.x, wid = tid >> 5, lane = tid & 31;
    int g = lane >> 2, tig = lane & 3;

    // ================= phase 1: prep (weights f16 / x transpose + norm) =================
    if (bid < 128) {
        int i = bid * 256 + tid;
        if (i < 24576) {
            float4 wv = ((const float4*)wqkv)[i];
            int c4 = (i & 63) << 2;
            float4 gv = *(const float4*)&gvec[c4];
            uint2 o;
            o.x = h2u(__floats2half2_rn(wv.x * gv.x, wv.y * gv.y));
            o.y = h2u(__floats2half2_rn(wv.z * gv.z, wv.w * gv.w));
            ((uint2*)g_wqh)[i] = o;
        } else {
            int j = i - 24576;
            float4 wv = ((const float4*)wout)[j];
            uint2 o;
            o.x = h2u(__floats2half2_rn(wv.x, wv.y));
            o.y = h2u(__floats2half2_rn(wv.z, wv.w));
            ((uint2*)g_woh)[j] = o;
        }
    } else {
        float* xs  = (float*)sm;
        float* ssq = xs + 64 * XSP;
        int pix0 = (bid - 128) * 64;
        int b = pix0 >> 12, p0 = pix0 & (N_PIX - 1);
        const float* xb = x + (size_t)b * CDIM * N_PIX + p0;
        __half* xh = g_xh + (size_t)(b * N_PIX + p0) * CDIM;
        int q = tid & 3, pw = tid >> 2;
        float ssp = 0.f;
        for (int chn = 0; chn < 4; chn++) {
#pragma unroll
            for (int k = 0; k < 4; k++) {
                int idx = tid + k * 256;
                int r = idx >> 4, c4 = (idx & 15) * 4;
                *(float4*)&xs[r * XSP + c4] =
                    *(const float4*)&xb[(size_t)(chn * 64 + r) * N_PIX + c4];
            }
            __syncthreads();
#pragma unroll
            for (int j = 0; j < 8; j++) {
                int c = 2 * q + 8 * j;
                float a = xs[c * XSP + pw];
                float bb = xs[(c + 1) * XSP + pw];
                ssp += a * a + bb * bb;
                *(__half2*)&xh[(size_t)pw * CDIM + chn * 64 + c] = __floats2half2_rn(a, bb);
            }
            __syncthreads();
        }
        ssq[tid] = ssp;
        __syncthreads();
        if (tid < 64) {
            float s = ssq[tid * 4] + ssq[tid * 4 + 1] + ssq[tid * 4 + 2] + ssq[tid * 4 + 3];
            g_scl[pix0 + tid] = 16.f / fmaxf(sqrtf(s), 1e-12f);
        }
    }
    grid_barrier();

    // ================= phase 2: QKV GEMM (192 items of 128x128, 1/CTA) =================
    if (bid < 192) {
        uint32_t* As = sm;                     // [4][128*GP]
        uint32_t* Bs = sm + 4 * 128 * GP;      // [4][128*GP]
        uint32_t sbA = smem_u32(As);
        uint32_t sbB = smem_u32(Bs);
        int pm = tid >> 1, ch = tid & 1;
        int wm = wid >> 2, wn = wid & 3;
        int lrA = ((lane >> 3) & 1) * 8 + (lane & 7);
        int lkA = (lane >> 4) * 4;
        int lrB = (lane >> 4) * 8 + (lane & 7);
        int lkB = ((lane >> 3) & 1) * 4;

        int b = bid / 96, rem = bid % 96;
        int row0 = (rem >> 5) * 128, col0 = (rem & 31) * 128;
        size_t bq = (size_t)b * N_PIX;

#define QKV_CP(it_, s_) do { \
        int k0q = (it_) * 16; \
        CP_ASYNC16(sbA + (s_) * (128 * GP * 4) + (pm * GP + ch * 4) * 4, \
                   (const char*)g_wqh + ((size_t)(row0 + pm) * CDIM + k0q + ch * 8) * 2); \
        CP_ASYNC16(sbB + (s_) * (128 * GP * 4) + (pm * GP + ch * 4) * 4, \
                   (const char*)g_xh + ((bq + col0 + pm) * CDIM + k0q + ch * 8) * 2); \
        CP_COMMIT(); \
    } while (0)

        QKV_CP(0, 0);
        QKV_CP(1, 1);
        QKV_CP(2, 2);

        float acc[4][4][4];
#pragma unroll
        for (int mi = 0; mi < 4; mi++)
#pragma unroll
            for (int ni = 0; ni < 4; ni++)
#pragma unroll
                for (int i = 0; i < 4; i++) acc[mi][ni][i] = 0.f;

        for (int it = 0; it < 16; it++) {
            int s = it & 3;
            CP_WAIT2();
            __syncthreads();
            if (it < 13) QKV_CP(it + 3, (it + 3) & 3);
            else CP_COMMIT();
            uint32_t af[4][4], bf[2][4];
#pragma unroll
            for (int mi = 0; mi < 4; mi++)
                LDSM_X4(af[mi][0], af[mi][1], af[mi][2], af[mi][3],
                        sbA + s * (128 * GP * 4) + ((wm * 64 + mi * 16 + lrA) * GP + lkA) * 4);
#pragma unroll
            for (int pr = 0; pr < 2; pr++)
                LDSM_X4(bf[pr][0], bf[pr][1], bf[pr][2], bf[pr][3],
                        sbB + s * (128 * GP * 4) + ((wn * 32 + pr * 16 + lrB) * GP + lkB) * 4);
#pragma unroll
            for (int ni = 0; ni < 4; ni++) {
                uint32_t b0 = bf[ni >> 1][(ni & 1) * 2];
                uint32_t b1 = bf[ni >> 1][(ni & 1) * 2 + 1];
#pragma unroll
                for (int mi = 0; mi < 4; mi++)
                    MMA_F16(acc[mi][ni], af[mi], b0, b1);
            }
        }
        CP_WAIT0();

        int t = row0 >> 7;
        float fac = (t == 0) ? (ATT_SCALE * LOG2E) : 1.f;
        const float* scl = g_scl + bq;
#pragma unroll
        for (int mi = 0; mi < 4; mi++) {
            int o_lo = row0 + wm * 64 + mi * 16 + g;
            int h = (o_lo >> 5) & 3;
            int f = o_lo & 31;
            size_t hb = (size_t)(b * NH + h);
#pragma unroll
            for (int ni = 0; ni < 4; ni++) {
                int p = col0 + wn * 32 + ni * 8 + 2 * tig;
                float s0 = scl[p] * fac, s1 = scl[p + 1] * fac;
                float c0 = acc[mi][ni][0] * s0, c1 = acc[mi][ni][1] * s1;
                float c2 = acc[mi][ni][2] * s0, c3 = acc[mi][ni][3] * s1;
                if (t < 2) {
                    __half* d = ((t == 0) ? g_qh : g_kh) + hb * N_PIX * DH;
                    d[(size_t)p * DH + f]           = __float2half_rn(c0);
                    d[(size_t)(p + 1) * DH + f]     = __float2half_rn(c1);
                    d[(size_t)p * DH + f + 8]       = __float2half_rn(c2);
                    d[(size_t)(p + 1) * DH + f + 8] = __float2half_rn(c3);
                } else {
                    __half* d = g_vh + hb * DH * N_PIX;
                    *(__half2*)&d[(size_t)f * N_PIX + p]       = __floats2half2_rn(c0, c1);
                    *(__half2*)&d[(size_t)(f + 8) * N_PIX + p] = __floats2half2_rn(c2, c3);
                }
            }
        }
    }
    grid_barrier();

    // ================= phase 3: flash attention (256 items) =================
    {
        int rL = lane & 7, kL = (lane >> 3) * 4;
        int bh = bid >> 5;
        int r0 = (bid & 31) * 128;
        int w = wid;
        int qb = r0 + w * 16;

        uint32_t sb = smem_u32(sm);
        const char* khp = (const char*)(g_kh + (size_t)bh * N_PIX * DH);
        const char* vhp = (const char*)(g_vh + (size_t)bh * DH * N_PIX);

        const __half* qp = g_qh + ((size_t)bh * N_PIX + qb) * DH;
        uint32_t qa[2][4];
#pragma unroll
        for (int kt = 0; kt < 2; kt++) {
            int chn = kt * 16 + 2 * tig;
            qa[kt][0] = *(const uint32_t*)&qp[g * DH + chn];
            qa[kt][1] = *(const uint32_t*)&qp[(g + 8) * DH + chn];
            qa[kt][2] = *(const uint32_t*)&qp[g * DH + chn + 8];
            qa[kt][3] = *(const uint32_t*)&qp[(g + 8) * DH + chn + 8];
        }

        float oacc[4][4];
#pragma unroll
        for (int nf = 0; nf < 4; nf++)
#pragma unroll
            for (int i = 0; i < 4; i++) oacc[nf][i] = 0.f;
        float lacc[4] = {0.f, 0.f, 0.f, 0.f};   // ones-MMA row sums: [0]=row g, [2]=row g+8

#pragma unroll
        for (int i = tid; i < 2048; i += 256) {
            if (i < 1024) {
                int row = i >> 2, cc = i & 3;
                CP_ASYNC16(sb + row * (KPW * 4) + cc * 16, khp + row * 64 + cc * 16);
            } else {
                int j = i - 1024, f = j >> 5, cc = j & 31;
                CP_ASYNC16(sb + 2 * KWRD * 4 + f * (VPW * 4) + cc * 16,
                           vhp + (size_t)f * 8192 + cc * 16);
            }
        }
        CP_COMMIT();

        for (int t = 0; t < 16; t++) {
            const char* ks = khp + (size_t)(t + 1) * 16384;
            const char* vs = vhp + (size_t)(t + 1) * 512;
            int nb = (t + 1) & 1;
            uint32_t kdst = sb + nb * KWRD * 4;
            uint32_t vdst = sb + (2 * KWRD + nb * VWRD) * 4;

            CP_WAIT0();
            __syncthreads();
            if (t < 15) {
#pragma unroll
                for (int i = tid; i < 2048; i += 256) {
                    if (i < 1024) {
                        int row = i >> 2, cc = i & 3;
                        CP_ASYNC16(kdst + row * (KPW * 4) + cc * 16, ks + row * 64 + cc * 16);
                    } else {
                        int j = i - 1024, f = j >> 5, cc = j & 31;
                        CP_ASYNC16(vdst + f * (VPW * 4) + cc * 16, vs + (size_t)f * 8192 + cc * 16);
                    }
                }
                CP_COMMIT();
            }
            uint32_t sbK = sb + (t & 1) * (KWRD * 4);
            uint32_t sbV = sb + (2 * KWRD + (t & 1) * VWRD) * 4;

#pragma unroll
            for (int chk = 0; chk < 8; chk++) {
                uint32_t kf[4][4], vf[4][4];
#pragma unroll
                for (int ni = 0; ni < 4; ni++)
                    LDSM_X4(kf[ni][0], kf[ni][1], kf[ni][2], kf[ni][3],
                            sbK + ((chk * 32 + ni * 8 + rL) * KPW + kL) * 4);
#pragma unroll
                for (int nf = 0; nf < 4; nf++)
                    LDSM_X4(vf[nf][0], vf[nf][1], vf[nf][2], vf[nf][3],
                            sbV + ((nf * 8 + rL) * VPW + chk * 16 + kL) * 4);
                float sacc[4][4];
#pragma unroll
                for (int ni = 0; ni < 4; ni++)
#pragma unroll
                    for (int i = 0; i < 4; i++) sacc[ni][i] = 0.f;
#pragma unroll
                for (int kt = 0; kt < 2; kt++)
#pragma unroll
                    for (int ni = 0; ni < 4; ni++)
                        MMA_F16(sacc[ni], qa[kt], kf[ni][2 * kt], kf[ni][2 * kt + 1]);
                uint32_t pf[4][2];
#pragma unroll
                for (int ni = 0; ni < 4; ni++) {
                    pf[ni][0] = ex2_h2(h2u(__floats2half2_rn(sacc[ni][0], sacc[ni][1])));
                    pf[ni][1] = ex2_h2(h2u(__floats2half2_rn(sacc[ni][2], sacc[ni][3])));
                }
                // O += P * V^T;  lacc += P * ones  (all on tensor pipe — it has headroom)
#pragma unroll
                for (int kt = 0; kt < 2; kt++) {
                    uint32_t pa[4];
                    pa[0] = pf[2 * kt][0];
                    pa[1] = pf[2 * kt][1];
                    pa[2] = pf[2 * kt + 1][0];
                    pa[3] = pf[2 * kt + 1][1];
#pragma unroll
                    for (int nf = 0; nf < 4; nf++)
                        MMA_F16(oacc[nf], pa, vf[nf][2 * kt], vf[nf][2 * kt + 1]);
                    MMA_F16(lacc, pa, ONES_H2, ONES_H2);
                }
            }
        }

        float inv0 = ATT_SCALE / lacc[0];
        float inv1 = ATT_SCALE / lacc[2];

        int b = bh >> 2, h = bh & 3;
        __half* ao = g_aoh + (size_t)b * N_PIX * HID + h * DH;
#pragma unroll
        for (int nf = 0; nf < 4; nf++) {
            int f = nf * 8 + 2 * tig;
            int rlo = qb + g, rhi = rlo + 8;
            *(__half2*)&ao[(size_t)rlo * HID + f] =
                __floats2half2_rn(oacc[nf][0] * inv0, oacc[nf][1] * inv0);
            *(__half2*)&ao[(size_t)rhi * HID + f] =
                __floats2half2_rn(oacc[nf][2] * inv1, oacc[nf][3] * inv1);
        }
    }
    grid_barrier();

    // ================= phase 4: output projection (256 items) =================
    {
        uint32_t* As = sm;
        uint32_t* Bs = sm + 4 * 64 * GP;
        uint32_t sbA = smem_u32(As);
        uint32_t sbB = smem_u32(Bs);
        int pm = tid >> 1, ch = tid & 1;
        int wm = wid >> 2, wn = wid & 3;
        int lrA = ((lane >> 3) & 1) * 8 + (lane & 7);
        int lkA = (lane >> 4) * 4;
        int lrB = (lane >> 4) * 8 + (lane & 7);
        int lkB = ((lane >> 3) & 1) * 4;

        int b = bid >> 7, rem = bid & 127;
        int row0 = (rem >> 5) * 64, col0 = (rem & 31) * 128;
        const char* Bsrc = (const char*)(g_aoh + (size_t)b * N_PIX * HID);

#define OUT_CP(it_, s_) do { \
        int k0q = (it_) * 16; \
        if (tid < 128) \
            CP_ASYNC16(sbA + (s_) * (64 * GP * 4) + (pm * GP + ch * 4) * 4, \
                       (const char*)g_woh + ((size_t)(row0 + pm) * HID + k0q + ch * 8) * 2); \
        CP_ASYNC16(sbB + (s_) * (128 * GP * 4) + (pm * GP + ch * 4) * 4, \
                   Bsrc + ((size_t)(col0 + pm) * HID + k0q + ch * 8) * 2); \
        CP_COMMIT(); \
    } while (0)

        OUT_CP(0, 0);
        OUT_CP(1, 1);
        OUT_CP(2, 2);

        float acc[2][4][4];
#pragma unroll
        for (int mi = 0; mi < 2; mi++)
#pragma unroll
            for (int ni = 0; ni < 4; ni++)
#pragma unroll
                for (int i = 0; i < 4; i++) acc[mi][ni][i] = 0.f;

        for (int it = 0; it < 8; it++) {
            int s = it & 3;
            CP_WAIT2();
            __syncthreads();
            if (it < 5) OUT_CP(it + 3, (it + 3) & 3);
            else CP_COMMIT();
            uint32_t af[2][4], bf[2][4];
#pragma unroll
            for (int mi = 0; mi < 2; mi++)
                LDSM_X4(af[mi][0], af[mi][1], af[mi][2], af[mi][3],
                        sbA + s * (64 * GP * 4) + ((wm * 32 + mi * 16 + lrA) * GP + lkA) * 4);
#pragma unroll
            for (int pr = 0; pr < 2; pr++)
                LDSM_X4(bf[pr][0], bf[pr][1], bf[pr][2], bf[pr][3],
                        sbB + s * (128 * GP * 4) + ((wn * 32 + pr * 16 + lrB) * GP + lkB) * 4);
#pragma unroll
            for (int ni = 0; ni < 4; ni++) {
                uint32_t b0 = bf[ni >> 1][(ni & 1) * 2];
                uint32_t b1 = bf[ni >> 1][(ni & 1) * 2 + 1];
#pragma unroll
                for (int mi = 0; mi < 2; mi++)
                    MMA_F16(acc[mi][ni], af[mi], b0, b1);
            }
        }
        CP_WAIT0();

#pragma unroll
        for (int mi = 0; mi < 2; mi++) {
            int o_lo = row0 + wm * 32 + mi * 16 + g;
            float b0v = bias[o_lo], b1v = bias[o_lo + 8];
            float* r0p = out + ((size_t)b * CDIM + o_lo) * N_PIX;
            float* r1p = r0p + 8 * N_PIX;
#pragma unroll
            for (int ni = 0; ni < 4; ni++) {
                int p = col0 + wn * 32 + ni * 8 + 2 * tig;
                *(float2*)&r0p[p] = make_float2(acc[mi][ni][0] + b0v, acc[mi][ni][1] + b0v);
                *(float2*)&r1p[p] = make_float2(acc[mi][ni][2] + b1v, acc[mi][ni][3] + b1v);
            }
        }
    }
}

// ---------------- launcher ----------------
extern "C" void kernel_launch(void* const* d_in, const int* in_sizes, int n_in,
                              void* d_out, int out_size) {
    const float* x     = (const float*)d_in[0];
    const float* gvec  = (const float*)d_in[1];
    const float* w_qkv = (const float*)d_in[2];
    const float* w_out = (const float*)d_in[3];
    const float* b_out = (const float*)d_in[4];
    float* out = (float*)d_out;

    static int smem_set = 0;
    if (!smem_set) {
        cudaFuncSetAttribute(fused, cudaFuncAttributeMaxDynamicSharedMemorySize,
                             SMEM_BYTES);
        smem_set = 1;
    }

    fused<<<GRID_N, 256, SMEM_BYTES>>>(x, gvec, w_qkv, w_out, b_out, out);
}